// round 1
// baseline (speedup 1.0000x reference)
#include <cuda_runtime.h>
#include <cuda_bf16.h>
#include <cstdio>

// Problem constants
#define M_TOK   131072      // b*s*a = 2*32*2048
#define EMB     512
#define NHEAD   8
#define HDIM    64
#define NGROUP  512         // b*s*h = 64*8
#define ALEN    2048
#define EPS_F   1e-6f

// Scratch buffers (device globals: allocation-free per harness rules)
__device__ float g_Q [(size_t)M_TOK * EMB];
__device__ float g_K [(size_t)M_TOK * EMB];
__device__ float g_V [(size_t)M_TOK * EMB];
__device__ float g_AO[(size_t)M_TOK * EMB];
__device__ float g_KtV[(size_t)NGROUP * HDIM * HDIM];
__device__ float g_ksum[(size_t)NGROUP * HDIM];

// ---------------------------------------------------------------------------
// GEMM: C[M,512] = act(A[M,512] @ W[512,512] + bias)
// ACT=0: identity, ACT=1: elu(x)+1 = (x>0 ? x+1 : exp(x))
// BM=128, BN=128, BK=8, 256 threads, 8x8 per thread.
// ---------------------------------------------------------------------------
template<int ACT>
__global__ __launch_bounds__(256, 2)
void gemm512_kernel(const float* __restrict__ A,
                    const float* __restrict__ W,
                    const float* __restrict__ bias,
                    float* __restrict__ C)
{
    constexpr int K = EMB, N = EMB;
    constexpr int BM = 128, BN = 128, BK = 8;

    __shared__ float As[BK][BM];   // transposed A tile
    __shared__ float Bs[BK][BN];

    const int bm = blockIdx.y * BM;
    const int bn = blockIdx.x * BN;
    const int t  = threadIdx.x;          // 0..255
    const int tx = t & 15;               // 0..15  (N direction)
    const int ty = t >> 4;               // 0..15  (M direction)

    // A tile load mapping: 128 rows x 8 cols = 256 float4
    const int arow = t >> 1;             // 0..127
    const int akv  = (t & 1) * 4;        // 0 or 4
    // B tile load mapping: 8 rows x 128 cols = 256 float4
    const int brow = t >> 5;             // 0..7
    const int bcol = (t & 31) * 4;       // 0..124

    const float* Aptr = A + (size_t)(bm + arow) * K + akv;
    const float* Wptr = W + (size_t)brow * N + bn + bcol;

    float acc[8][8];
    #pragma unroll
    for (int i = 0; i < 8; i++)
        #pragma unroll
        for (int j = 0; j < 8; j++)
            acc[i][j] = 0.f;

    for (int k0 = 0; k0 < K; k0 += BK) {
        float4 av = *(const float4*)(Aptr + k0);
        As[akv + 0][arow] = av.x;
        As[akv + 1][arow] = av.y;
        As[akv + 2][arow] = av.z;
        As[akv + 3][arow] = av.w;
        *(float4*)&Bs[brow][bcol] = *(const float4*)(Wptr + (size_t)k0 * N);
        __syncthreads();

        #pragma unroll
        for (int k = 0; k < BK; k++) {
            float af[8], bf[8];
            *(float4*)&af[0] = *(const float4*)&As[k][ty * 8];
            *(float4*)&af[4] = *(const float4*)&As[k][ty * 8 + 4];
            *(float4*)&bf[0] = *(const float4*)&Bs[k][tx * 8];
            *(float4*)&bf[4] = *(const float4*)&Bs[k][tx * 8 + 4];
            #pragma unroll
            for (int i = 0; i < 8; i++)
                #pragma unroll
                for (int j = 0; j < 8; j++)
                    acc[i][j] += af[i] * bf[j];
        }
        __syncthreads();
    }

    // epilogue
    float bb[8];
    #pragma unroll
    for (int j = 0; j < 8; j++) bb[j] = bias[bn + tx * 8 + j];

    #pragma unroll
    for (int i = 0; i < 8; i++) {
        const size_t row = (size_t)(bm + ty * 8 + i);
        #pragma unroll
        for (int j0 = 0; j0 < 8; j0 += 4) {
            float4 o;
            float v0 = acc[i][j0 + 0] + bb[j0 + 0];
            float v1 = acc[i][j0 + 1] + bb[j0 + 1];
            float v2 = acc[i][j0 + 2] + bb[j0 + 2];
            float v3 = acc[i][j0 + 3] + bb[j0 + 3];
            if (ACT == 1) {
                v0 = v0 > 0.f ? v0 + 1.f : expf(v0);
                v1 = v1 > 0.f ? v1 + 1.f : expf(v1);
                v2 = v2 > 0.f ? v2 + 1.f : expf(v2);
                v3 = v3 > 0.f ? v3 + 1.f : expf(v3);
            }
            o.x = v0; o.y = v1; o.z = v2; o.w = v3;
            *(float4*)(C + row * N + bn + tx * 8 + j0) = o;
        }
    }
}

// ---------------------------------------------------------------------------
// KtV + ksum: per group g=(bs,h): KtV[d,e] = sum_a K[a,d]*V[a,e]; ksum[d]=sum_a K[a,d]
// One block per group (512 blocks), 256 threads, 4x4 per thread, a-chunks of 32.
// ---------------------------------------------------------------------------
__global__ __launch_bounds__(256, 2)
void ktv_kernel(const float* __restrict__ Kp,
                const float* __restrict__ Vp,
                float* __restrict__ KtV,
                float* __restrict__ ksum)
{
    const int g  = blockIdx.x;          // 0..511
    const int bs = g >> 3;
    const int h  = g & 7;
    const size_t rowbase = (size_t)bs * ALEN;
    const int coff = h * HDIM;

    __shared__ float Ks[32][HDIM];
    __shared__ float Vs[32][HDIM];

    const int t  = threadIdx.x;
    const int tx = t & 15;
    const int ty = t >> 4;

    float acc[4][4];
    #pragma unroll
    for (int i = 0; i < 4; i++)
        #pragma unroll
        for (int j = 0; j < 4; j++)
            acc[i][j] = 0.f;
    float kcol = 0.f;

    for (int a0 = 0; a0 < ALEN; a0 += 32) {
        #pragma unroll
        for (int i = 0; i < 2; i++) {
            const int idx = t * 2 + i;          // 0..511
            const int r   = idx >> 4;           // 0..31
            const int c4  = (idx & 15) * 4;     // 0..60
            const size_t goff = (rowbase + a0 + r) * EMB + coff + c4;
            *(float4*)&Ks[r][c4] = *(const float4*)(Kp + goff);
            *(float4*)&Vs[r][c4] = *(const float4*)(Vp + goff);
        }
        __syncthreads();

        #pragma unroll 8
        for (int r = 0; r < 32; r++) {
            float kf[4], vf[4];
            *(float4*)kf = *(const float4*)&Ks[r][ty * 4];
            *(float4*)vf = *(const float4*)&Vs[r][tx * 4];
            #pragma unroll
            for (int i = 0; i < 4; i++)
                #pragma unroll
                for (int j = 0; j < 4; j++)
                    acc[i][j] += kf[i] * vf[j];
        }
        if (t < HDIM) {
            #pragma unroll 8
            for (int r = 0; r < 32; r++) kcol += Ks[r][t];
        }
        __syncthreads();
    }

    float* out = KtV + (size_t)g * HDIM * HDIM;
    #pragma unroll
    for (int i = 0; i < 4; i++)
        #pragma unroll
        for (int j = 0; j < 4; j++)
            out[(ty * 4 + i) * HDIM + tx * 4 + j] = acc[i][j];
    if (t < HDIM) ksum[(size_t)g * HDIM + t] = kcol;
}

// ---------------------------------------------------------------------------
// Apply: per token/head: z = 1/(q.ksum + eps); AO = z * (q @ KtV)
// grid (16 a-tiles, 512 groups), 128 threads, 1 token per thread.
// ---------------------------------------------------------------------------
__global__ __launch_bounds__(128, 4)
void apply_kernel(const float* __restrict__ Qp,
                  const float* __restrict__ KtV,
                  const float* __restrict__ ksum,
                  float* __restrict__ AO)
{
    const int g    = blockIdx.y;
    const int tile = blockIdx.x;
    const int bs   = g >> 3;
    const int h    = g & 7;

    __shared__ float sKtV[HDIM][HDIM];
    __shared__ float sks[HDIM];

    const int t = threadIdx.x;
    {
        const float4* src = (const float4*)(KtV + (size_t)g * HDIM * HDIM);
        float4* dst = (float4*)&sKtV[0][0];
        #pragma unroll
        for (int i = t; i < HDIM * HDIM / 4; i += 128) dst[i] = src[i];
        if (t < HDIM) sks[t] = ksum[(size_t)g * HDIM + t];
    }
    __syncthreads();

    const int a = tile * 128 + t;
    const size_t off = ((size_t)bs * ALEN + a) * EMB + h * HDIM;

    float q[HDIM];
    {
        const float4* qp = (const float4*)(Qp + off);
        #pragma unroll
        for (int i = 0; i < HDIM / 4; i++) ((float4*)q)[i] = qp[i];
    }

    float dot = 0.f;
    #pragma unroll
    for (int d = 0; d < HDIM; d++) dot += q[d] * sks[d];
    const float z = 1.f / (dot + EPS_F);

    #pragma unroll
    for (int e4 = 0; e4 < HDIM; e4 += 4) {
        float ax = 0.f, ay = 0.f, az = 0.f, aw = 0.f;
        #pragma unroll
        for (int d = 0; d < HDIM; d++) {
            const float4 kv = *(const float4*)&sKtV[d][e4];
            const float qd = q[d];
            ax += qd * kv.x; ay += qd * kv.y;
            az += qd * kv.z; aw += qd * kv.w;
        }
        float4 o;
        o.x = z * ax; o.y = z * ay; o.z = z * az; o.w = z * aw;
        *(float4*)(AO + off + e4) = o;
    }
}

// ---------------------------------------------------------------------------
extern "C" void kernel_launch(void* const* d_in, const int* in_sizes, int n_in,
                              void* d_out, int out_size)
{
    const float* input_q  = (const float*)d_in[0];
    const float* input_kv = (const float*)d_in[1];
    const float* Wq = (const float*)d_in[2];
    const float* bq = (const float*)d_in[3];
    const float* Wk = (const float*)d_in[4];
    const float* bk = (const float*)d_in[5];
    const float* Wv = (const float*)d_in[6];
    const float* bv = (const float*)d_in[7];
    const float* Wo = (const float*)d_in[8];
    const float* bo = (const float*)d_in[9];
    float* out = (float*)d_out;

    // Resolve device-global scratch (no allocation; capture-safe host query)
    void *pQ, *pK, *pV, *pAO, *pKtV, *pks;
    cudaGetSymbolAddress(&pQ,   g_Q);
    cudaGetSymbolAddress(&pK,   g_K);
    cudaGetSymbolAddress(&pV,   g_V);
    cudaGetSymbolAddress(&pAO,  g_AO);
    cudaGetSymbolAddress(&pKtV, g_KtV);
    cudaGetSymbolAddress(&pks,  g_ksum);
    float* Q   = (float*)pQ;
    float* Kb  = (float*)pK;
    float* Vb  = (float*)pV;
    float* AO  = (float*)pAO;
    float* KtV = (float*)pKtV;
    float* ks  = (float*)pks;

    const dim3 ggrid(EMB / 128, M_TOK / 128);   // (4, 1024)
    const dim3 gblk(256);

    // Projections (elu+1 fused for Q,K)
    gemm512_kernel<1><<<ggrid, gblk>>>(input_q,  Wq, bq, Q);
    gemm512_kernel<1><<<ggrid, gblk>>>(input_kv, Wk, bk, Kb);
    gemm512_kernel<0><<<ggrid, gblk>>>(input_kv, Wv, bv, Vb);

    // Linear attention core
    ktv_kernel<<<NGROUP, 256>>>(Kb, Vb, KtV, ks);
    apply_kernel<<<dim3(ALEN / 128, NGROUP), 128>>>(Q, KtV, ks, AO);

    // Output projection
    gemm512_kernel<0><<<ggrid, gblk>>>(AO, Wo, bo, out);
}

// round 3
// speedup vs baseline: 1.1244x; 1.1244x over previous
#include <cuda_runtime.h>
#include <cuda_bf16.h>
#include <cstdint>

// Problem constants
#define M_TOK   131072      // b*s*a = 2*32*2048
#define EMB     512
#define NHEAD   8
#define HDIM    64
#define NGROUP  512         // b*s*h = 64*8
#define ALEN    2048
#define EPS_F   1e-6f
#define KSPLIT  4
#define ACH     (ALEN / KSPLIT)   // 512

// Scratch (device globals: allocation-free per harness rules)
__device__ float g_Q [(size_t)M_TOK * EMB];
__device__ float g_K [(size_t)M_TOK * EMB];
__device__ float g_V [(size_t)M_TOK * EMB];
__device__ float g_AO[(size_t)M_TOK * EMB];
__device__ float g_KtVp [(size_t)KSPLIT * NGROUP * HDIM * HDIM];
__device__ float g_ksump[(size_t)KSPLIT * NGROUP * HDIM];
__device__ float g_KtV  [(size_t)NGROUP * HDIM * HDIM];
__device__ float g_ksum [(size_t)NGROUP * HDIM];

// ---------------------------------------------------------------------------
__device__ __forceinline__ uint32_t f2tf(float f) {
    uint32_t r;
    asm("cvt.rna.tf32.f32 %0, %1;" : "=r"(r) : "f"(f));
    return r;
}

__device__ __forceinline__ void mma8(float* d, const uint32_t* a, const uint32_t* b) {
    asm volatile(
        "mma.sync.aligned.m16n8k8.row.col.f32.tf32.tf32.f32 "
        "{%0,%1,%2,%3},{%4,%5,%6,%7},{%8,%9},{%0,%1,%2,%3};"
        : "+f"(d[0]), "+f"(d[1]), "+f"(d[2]), "+f"(d[3])
        : "r"(a[0]), "r"(a[1]), "r"(a[2]), "r"(a[3]),
          "r"(b[0]), "r"(b[1]));
}

// ===========================================================================
// tf32 tensor-core GEMM: C[M,512] = act(A[M,512] @ W[512,512] + bias)
// W is [K,N] row-major, which directly matches the mma .col B-fragment
// (B[k][n] scattered per-lane), so no weight transpose is needed.
// BM=64, BN=256, BK=32. 512 threads = 16 warps (2 M x 8 N), warp tile 32x32.
// SMEM holds operands pre-arranged in mma fragment layout:
//   AsF[mtile(4)*4+ks(4)][lane(32)][4 regs]  (tf32 bits)
//   BsF[ntile(32)*4+ks(4)][lane(32)][2 regs]
// with per-block lane rotation (lane + 2*blk)&31 to spread scatter-store banks.
// ACT=0 identity, ACT=1 elu(x)+1.
// ===========================================================================
template<int ACT>
__global__ __launch_bounds__(512, 2)
void gemm_mma_kernel(const float* __restrict__ A,
                     const float* __restrict__ W,
                     const float* __restrict__ bias,
                     float* __restrict__ C)
{
    __shared__ uint32_t AsF[2048];   // 8KB
    __shared__ uint32_t BsF[8192];   // 32KB

    const int t   = threadIdx.x;
    const int lid = t & 31;
    const int wid = t >> 5;          // 0..15
    const int wr  = wid >> 3;        // 0..1  (M)
    const int wc  = wid & 7;         // 0..7  (N)
    const int bn  = blockIdx.x * 256;
    const int bm  = blockIdx.y * 64;

    float acc[2][4][4];
    #pragma unroll
    for (int i = 0; i < 2; i++)
        #pragma unroll
        for (int j = 0; j < 4; j++)
            #pragma unroll
            for (int k = 0; k < 4; k++)
                acc[i][j][k] = 0.f;

    // A loader: one float4 per thread per chunk
    const int arow = t >> 3;         // 0..63
    const int ac4  = t & 7;          // 0..7
    const float* Ag = A + (size_t)(bm + arow) * EMB + ac4 * 4;

    for (int c = 0; c < 16; c++) {
        const int k0 = c * 32;

        // global loads (issued early; latency overlaps previous compute)
        const float4 av = *(const float4*)(Ag + k0);
        float4 bv[4];
        #pragma unroll
        for (int i = 0; i < 4; i++) {
            const int f4   = t + i * 512;
            const int krow = f4 >> 6;        // 0..31
            const int nf4  = f4 & 63;        // 0..63
            bv[i] = *(const float4*)(W + (size_t)(k0 + krow) * EMB + bn + nf4 * 4);
        }

        __syncthreads();   // previous chunk fully consumed

        // scatter A into fragment layout (with tf32 rounding)
        {
            const int r  = arow & 15;
            const int mt = arow >> 4;
            #pragma unroll
            for (int e = 0; e < 4; e++) {
                const int k  = ac4 * 4 + e;
                const int ks = k >> 3, kk = k & 7;
                const int lf = (r & 7) * 4 + (kk & 3);
                const int rg = ((kk >> 2) << 1) | (r >> 3);
                const int bI = mt * 4 + ks;
                AsF[(bI * 32 + ((lf + 2 * bI) & 31)) * 4 + rg] =
                    f2tf(((const float*)&av)[e]);
            }
        }
        // scatter B
        #pragma unroll
        for (int i = 0; i < 4; i++) {
            const int f4   = t + i * 512;
            const int krow = f4 >> 6;
            const int nf4  = f4 & 63;
            const int ks   = krow >> 3, kk = krow & 7;
            #pragma unroll
            for (int e = 0; e < 4; e++) {
                const int nl = nf4 * 4 + e;          // 0..255
                const int nt = nl >> 3, nn = nl & 7;
                const int lf = nn * 4 + (kk & 3);
                const int rg = kk >> 2;
                const int bI = nt * 4 + ks;
                BsF[(bI * 32 + ((lf + 2 * bI) & 31)) * 2 + rg] =
                    f2tf(((const float*)&bv[i])[e]);
            }
        }
        __syncthreads();

        // compute: 4 k-steps x (2 mtiles x 4 ntiles) mma
        #pragma unroll
        for (int ks = 0; ks < 4; ks++) {
            uint32_t aF[2][4];
            uint32_t bF[4][2];
            #pragma unroll
            for (int m2 = 0; m2 < 2; m2++) {
                const int bI = (wr * 2 + m2) * 4 + ks;
                const int lp = (lid + 2 * bI) & 31;
                const uint4 v = *(const uint4*)&AsF[(bI * 32 + lp) * 4];
                aF[m2][0] = v.x; aF[m2][1] = v.y; aF[m2][2] = v.z; aF[m2][3] = v.w;
            }
            #pragma unroll
            for (int n2 = 0; n2 < 4; n2++) {
                const int bI = (wc * 4 + n2) * 4 + ks;
                const int lp = (lid + 2 * bI) & 31;
                const uint2 v = *(const uint2*)&BsF[(bI * 32 + lp) * 2];
                bF[n2][0] = v.x; bF[n2][1] = v.y;
            }
            #pragma unroll
            for (int m2 = 0; m2 < 2; m2++)
                #pragma unroll
                for (int n2 = 0; n2 < 4; n2++)
                    mma8(acc[m2][n2], aF[m2], bF[n2]);
        }
    }

    // epilogue: bias + optional elu+1, direct fp32 stores
    const int r0 = bm + wr * 32 + (lid >> 2);
    #pragma unroll
    for (int m2 = 0; m2 < 2; m2++) {
        const int row = r0 + m2 * 16;
        #pragma unroll
        for (int n2 = 0; n2 < 4; n2++) {
            const int col = bn + wc * 32 + n2 * 8 + (lid & 3) * 2;
            const float b0 = __ldg(bias + col);
            const float b1 = __ldg(bias + col + 1);
            float v0 = acc[m2][n2][0] + b0;
            float v1 = acc[m2][n2][1] + b1;
            float v2 = acc[m2][n2][2] + b0;
            float v3 = acc[m2][n2][3] + b1;
            if (ACT == 1) {
                v0 = v0 > 0.f ? v0 + 1.f : expf(v0);
                v1 = v1 > 0.f ? v1 + 1.f : expf(v1);
                v2 = v2 > 0.f ? v2 + 1.f : expf(v2);
                v3 = v3 > 0.f ? v3 + 1.f : expf(v3);
            }
            float2 o0; o0.x = v0; o0.y = v1;
            float2 o1; o1.x = v2; o1.y = v3;
            *(float2*)(C + (size_t)row * EMB + col) = o0;
            *(float2*)(C + (size_t)(row + 8) * EMB + col) = o1;
        }
    }
}

// ---------------------------------------------------------------------------
// KtV + ksum, split 4-way over the attention axis (grid.y = chunk)
// ---------------------------------------------------------------------------
__global__ __launch_bounds__(256, 2)
void ktv_kernel(const float* __restrict__ Kp,
                const float* __restrict__ Vp,
                float* __restrict__ KtVp,
                float* __restrict__ ksump)
{
    const int g  = blockIdx.x;          // 0..511
    const int ch = blockIdx.y;          // 0..3
    const int bs = g >> 3;
    const int h  = g & 7;
    const size_t rowbase = (size_t)bs * ALEN;
    const int coff = h * HDIM;

    __shared__ float Ks[32][HDIM];
    __shared__ float Vs[32][HDIM];

    const int t  = threadIdx.x;
    const int tx = t & 15;
    const int ty = t >> 4;

    float acc[4][4];
    #pragma unroll
    for (int i = 0; i < 4; i++)
        #pragma unroll
        for (int j = 0; j < 4; j++)
            acc[i][j] = 0.f;
    float kcol = 0.f;

    for (int a0 = ch * ACH; a0 < (ch + 1) * ACH; a0 += 32) {
        #pragma unroll
        for (int i = 0; i < 2; i++) {
            const int idx = t * 2 + i;
            const int r   = idx >> 4;
            const int c4  = (idx & 15) * 4;
            const size_t goff = (rowbase + a0 + r) * EMB + coff + c4;
            *(float4*)&Ks[r][c4] = *(const float4*)(Kp + goff);
            *(float4*)&Vs[r][c4] = *(const float4*)(Vp + goff);
        }
        __syncthreads();

        #pragma unroll 8
        for (int r = 0; r < 32; r++) {
            float kf[4], vf[4];
            *(float4*)kf = *(const float4*)&Ks[r][ty * 4];
            *(float4*)vf = *(const float4*)&Vs[r][tx * 4];
            #pragma unroll
            for (int i = 0; i < 4; i++)
                #pragma unroll
                for (int j = 0; j < 4; j++)
                    acc[i][j] += kf[i] * vf[j];
        }
        if (t < HDIM) {
            #pragma unroll 8
            for (int r = 0; r < 32; r++) kcol += Ks[r][t];
        }
        __syncthreads();
    }

    float* out = KtVp + ((size_t)ch * NGROUP + g) * HDIM * HDIM;
    #pragma unroll
    for (int i = 0; i < 4; i++)
        #pragma unroll
        for (int j = 0; j < 4; j++)
            out[(ty * 4 + i) * HDIM + tx * 4 + j] = acc[i][j];
    if (t < HDIM) ksump[((size_t)ch * NGROUP + g) * HDIM + t] = kcol;
}

// ---------------------------------------------------------------------------
// Reduce the 4 KtV/ksum partials
// ---------------------------------------------------------------------------
__global__ __launch_bounds__(256)
void ktv_reduce_kernel(const float* __restrict__ KtVp,
                       const float* __restrict__ ksump,
                       float* __restrict__ KtV,
                       float* __restrict__ ksum)
{
    const int g = blockIdx.x;
    const int t = threadIdx.x;
    #pragma unroll
    for (int i = t; i < HDIM * HDIM; i += 256) {
        float s = 0.f;
        #pragma unroll
        for (int p = 0; p < KSPLIT; p++)
            s += KtVp[((size_t)p * NGROUP + g) * HDIM * HDIM + i];
        KtV[(size_t)g * HDIM * HDIM + i] = s;
    }
    if (t < HDIM) {
        float s = 0.f;
        #pragma unroll
        for (int p = 0; p < KSPLIT; p++)
            s += ksump[((size_t)p * NGROUP + g) * HDIM + t];
        ksum[(size_t)g * HDIM + t] = s;
    }
}

// ---------------------------------------------------------------------------
// Apply: per token/head: z = 1/(q.ksum + eps); AO = z * (q @ KtV)
// ---------------------------------------------------------------------------
__global__ __launch_bounds__(128, 4)
void apply_kernel(const float* __restrict__ Qp,
                  const float* __restrict__ KtV,
                  const float* __restrict__ ksum,
                  float* __restrict__ AO)
{
    const int g    = blockIdx.y;
    const int tile = blockIdx.x;
    const int bs   = g >> 3;
    const int h    = g & 7;

    __shared__ float sKtV[HDIM][HDIM];
    __shared__ float sks[HDIM];

    const int t = threadIdx.x;
    {
        const float4* src = (const float4*)(KtV + (size_t)g * HDIM * HDIM);
        float4* dst = (float4*)&sKtV[0][0];
        #pragma unroll
        for (int i = t; i < HDIM * HDIM / 4; i += 128) dst[i] = src[i];
        if (t < HDIM) sks[t] = ksum[(size_t)g * HDIM + t];
    }
    __syncthreads();

    const int a = tile * 128 + t;
    const size_t off = ((size_t)bs * ALEN + a) * EMB + h * HDIM;

    float q[HDIM];
    {
        const float4* qp = (const float4*)(Qp + off);
        #pragma unroll
        for (int i = 0; i < HDIM / 4; i++) ((float4*)q)[i] = qp[i];
    }

    float dot = 0.f;
    #pragma unroll
    for (int d = 0; d < HDIM; d++) dot += q[d] * sks[d];
    const float z = 1.f / (dot + EPS_F);

    #pragma unroll
    for (int e4 = 0; e4 < HDIM; e4 += 4) {
        float ax = 0.f, ay = 0.f, az = 0.f, aw = 0.f;
        #pragma unroll
        for (int d = 0; d < HDIM; d++) {
            const float4 kv = *(const float4*)&sKtV[d][e4];
            const float qd = q[d];
            ax += qd * kv.x; ay += qd * kv.y;
            az += qd * kv.z; aw += qd * kv.w;
        }
        float4 o;
        o.x = z * ax; o.y = z * ay; o.z = z * az; o.w = z * aw;
        *(float4*)(AO + off + e4) = o;
    }
}

// ---------------------------------------------------------------------------
extern "C" void kernel_launch(void* const* d_in, const int* in_sizes, int n_in,
                              void* d_out, int out_size)
{
    const float* input_q  = (const float*)d_in[0];
    const float* input_kv = (const float*)d_in[1];
    const float* Wq = (const float*)d_in[2];
    const float* bq = (const float*)d_in[3];
    const float* Wk = (const float*)d_in[4];
    const float* bk = (const float*)d_in[5];
    const float* Wv = (const float*)d_in[6];
    const float* bv = (const float*)d_in[7];
    const float* Wo = (const float*)d_in[8];
    const float* bo = (const float*)d_in[9];
    float* out = (float*)d_out;

    void *pQ, *pK, *pV, *pAO, *pKtVp, *pksp, *pKtV, *pks;
    cudaGetSymbolAddress(&pQ,    g_Q);
    cudaGetSymbolAddress(&pK,    g_K);
    cudaGetSymbolAddress(&pV,    g_V);
    cudaGetSymbolAddress(&pAO,   g_AO);
    cudaGetSymbolAddress(&pKtVp, g_KtVp);
    cudaGetSymbolAddress(&pksp,  g_ksump);
    cudaGetSymbolAddress(&pKtV,  g_KtV);
    cudaGetSymbolAddress(&pks,   g_ksum);
    float* Q    = (float*)pQ;
    float* Kb   = (float*)pK;
    float* Vb   = (float*)pV;
    float* AO   = (float*)pAO;
    float* KtVp = (float*)pKtVp;
    float* ksp  = (float*)pksp;
    float* KtV  = (float*)pKtV;
    float* ks   = (float*)pks;

    const dim3 ggrid(EMB / 256, M_TOK / 64);   // (2, 2048)

    // Projections on tensor cores via mma.sync tf32 (elu+1 fused for Q,K)
    gemm_mma_kernel<1><<<ggrid, 512>>>(input_q,  Wq, bq, Q);
    gemm_mma_kernel<1><<<ggrid, 512>>>(input_kv, Wk, bk, Kb);
    gemm_mma_kernel<0><<<ggrid, 512>>>(input_kv, Wv, bv, Vb);

    // Linear attention core
    ktv_kernel<<<dim3(NGROUP, KSPLIT), 256>>>(Kb, Vb, KtVp, ksp);
    ktv_reduce_kernel<<<NGROUP, 256>>>(KtVp, ksp, KtV, ks);
    apply_kernel<<<dim3(ALEN / 128, NGROUP), 128>>>(Q, KtV, ks, AO);

    // Output projection
    gemm_mma_kernel<0><<<ggrid, 512>>>(AO, Wo, bo, out);
}

// round 4
// speedup vs baseline: 2.5024x; 2.2255x over previous
#include <cuda_runtime.h>
#include <cuda_bf16.h>
#include <cstdint>

// Problem constants
#define M_TOK   131072      // b*s*a = 2*32*2048
#define EMB     512
#define NHEAD   8
#define HDIM    64
#define NGROUP  512         // b*s*h = 64*8
#define ALEN    2048
#define EPS_F   1e-6f
#define KSPLIT  4
#define ACH     (ALEN / KSPLIT)   // 512

// Scratch (device globals: allocation-free per harness rules)
__device__ float    g_Q [(size_t)M_TOK * EMB];
__device__ float    g_K [(size_t)M_TOK * EMB];
__device__ float    g_V [(size_t)M_TOK * EMB];
__device__ float    g_AO[(size_t)M_TOK * EMB];
__device__ float    g_KtVp [(size_t)KSPLIT * NGROUP * HDIM * HDIM];
__device__ float    g_ksump[(size_t)KSPLIT * NGROUP * HDIM];
__device__ float    g_KtV  [(size_t)NGROUP * HDIM * HDIM];
__device__ float    g_ksum [(size_t)NGROUP * HDIM];
__device__ uint32_t g_Wf [4 * (size_t)EMB * EMB];   // fragment-permuted tf32 weights

// ---------------------------------------------------------------------------
__device__ __forceinline__ uint32_t f2tf(float f) {
    uint32_t r;
    asm("cvt.rna.tf32.f32 %0, %1;" : "=r"(r) : "f"(f));
    return r;
}

__device__ __forceinline__ void mma8(float* d, const uint32_t* a, const uint32_t* b) {
    asm volatile(
        "mma.sync.aligned.m16n8k8.row.col.f32.tf32.tf32.f32 "
        "{%0,%1,%2,%3},{%4,%5,%6,%7},{%8,%9},{%0,%1,%2,%3};"
        : "+f"(d[0]), "+f"(d[1]), "+f"(d[2]), "+f"(d[3])
        : "r"(a[0]), "r"(a[1]), "r"(a[2]), "r"(a[3]),
          "r"(b[0]), "r"(b[1]));
}

// Validated fragment mapping (round-3 pass is ground truth):
//   A (m16n8k8): lane l, reg rg holds A[(l>>2)+8*(rg&1)][(l&3)+4*(rg>>1)]
//   B:           lane l, reg rg holds B[k=(l&3)+4*rg][n=(l>>2)]
//   C:           lane l, reg c:  row=(l>>2)+8*(c>>1), col=(l&3)*2+(c&1)

// ===========================================================================
// Weight prep: permute W[512,512] ([K,N] row-major) into fragment order:
//   Wf[c(16)][ks(4)][ntg(64)][lane(32)][rg(2)] = tf32(W[c*32+ks*8+(l&3)+4*rg][ntg*8+(l>>2)])
// ===========================================================================
__global__ __launch_bounds__(256)
void wprep_kernel(const float* __restrict__ W, uint32_t* __restrict__ Wf)
{
    const int o   = blockIdx.x * 256 + threadIdx.x;   // 0..262143
    const int rg  = o & 1;
    const int l   = (o >> 1) & 31;
    const int ntg = (o >> 6) & 63;
    const int ks  = (o >> 12) & 3;
    const int c   = o >> 14;
    const int k   = c * 32 + ks * 8 + (l & 3) + 4 * rg;
    const int n   = ntg * 8 + (l >> 2);
    Wf[o] = f2tf(W[(size_t)k * EMB + n]);
}

// ===========================================================================
// tf32 mma GEMM: C[M,512] = act(A[M,512] @ W + bias), W pre-permuted.
// BM=64, BN=256, BK=32. 512 threads = 16 warps (2 M x 8 N), warp tile 32x32.
// A: SMEM stride-36 rows (conflict-free STS.128 + fragment LDS.32).
// B: coalesced uint4 copy of pre-permuted gmem; conflict-free LDS.64 gathers.
// Double-buffered, one __syncthreads per chunk.
// ===========================================================================
#define GAS_W   (64 * 36)     // A buffer words
#define GBS_W   8192          // B buffer words
#define GEMM_SMEM ((2 * GAS_W + 2 * GBS_W) * 4)   // 83968 B

template<int ACT>
__global__ __launch_bounds__(512)
void gemm_mma2_kernel(const float* __restrict__ A,
                      const uint32_t* __restrict__ Wf,
                      const float* __restrict__ bias,
                      float* __restrict__ C)
{
    extern __shared__ uint32_t sm[];
    uint32_t* As = sm;                 // [2][64][36]
    uint32_t* Bs = sm + 2 * GAS_W;     // [2][8192]

    const int t   = threadIdx.x;
    const int lid = t & 31;
    const int wid = t >> 5;
    const int wr  = wid >> 3;          // 0..1 (M)
    const int wc  = wid & 7;           // 0..7 (N)
    const int bx  = blockIdx.x;        // 0..1 (N half)
    const int bm  = blockIdx.y * 64;

    const int arow = t >> 3;           // 0..63
    const int ac4  = t & 7;            // 0..7
    const float* Ag = A + (size_t)(bm + arow) * EMB + ac4 * 4;
    const uint4* Wf4 = (const uint4*)Wf;

    float acc[2][4][4];
    #pragma unroll
    for (int i = 0; i < 2; i++)
        #pragma unroll
        for (int j = 0; j < 4; j++)
            #pragma unroll
            for (int k = 0; k < 4; k++)
                acc[i][j][k] = 0.f;

    // preload chunk 0
    float4 aReg = *(const float4*)Ag;
    uint4 bReg[4];
    #pragma unroll
    for (int s = 0; s < 4; s++)
        bReg[s] = Wf4[(size_t)((0 * 4 + s) * 64 + bx * 32) * 16 + t];

    for (int c = 0; c < 16; c++) {
        const int buf = c & 1;
        uint32_t* Ab = As + buf * GAS_W;
        uint32_t* Bb = Bs + buf * GBS_W;

        // store staged chunk
        {
            uint4 av;
            av.x = f2tf(aReg.x); av.y = f2tf(aReg.y);
            av.z = f2tf(aReg.z); av.w = f2tf(aReg.w);
            *(uint4*)&Ab[arow * 36 + ac4 * 4] = av;
            #pragma unroll
            for (int s = 0; s < 4; s++)
                ((uint4*)Bb)[s * 512 + t] = bReg[s];
        }
        __syncthreads();

        // prefetch next chunk
        if (c < 15) {
            aReg = *(const float4*)(Ag + (c + 1) * 32);
            #pragma unroll
            for (int s = 0; s < 4; s++)
                bReg[s] = Wf4[(size_t)(((c + 1) * 4 + s) * 64 + bx * 32) * 16 + t];
        }

        // compute
        #pragma unroll
        for (int ks = 0; ks < 4; ks++) {
            uint32_t aF[2][4];
            #pragma unroll
            for (int m2 = 0; m2 < 2; m2++)
                #pragma unroll
                for (int rg = 0; rg < 4; rg++) {
                    const int row = wr * 32 + m2 * 16 + (lid >> 2) + 8 * (rg & 1);
                    const int k   = ks * 8 + (lid & 3) + 4 * (rg >> 1);
                    aF[m2][rg] = Ab[row * 36 + k];
                }
            uint32_t bF[4][2];
            #pragma unroll
            for (int n2 = 0; n2 < 4; n2++) {
                const uint2 v = *(const uint2*)&Bb[((ks * 32 + wc * 4 + n2) * 32 + lid) * 2];
                bF[n2][0] = v.x; bF[n2][1] = v.y;
            }
            #pragma unroll
            for (int m2 = 0; m2 < 2; m2++)
                #pragma unroll
                for (int n2 = 0; n2 < 4; n2++)
                    mma8(acc[m2][n2], aF[m2], bF[n2]);
        }
        __syncthreads();
    }

    // epilogue (validated layout)
    const int bn = bx * 256;
    const int r0 = bm + wr * 32 + (lid >> 2);
    #pragma unroll
    for (int m2 = 0; m2 < 2; m2++) {
        const int row = r0 + m2 * 16;
        #pragma unroll
        for (int n2 = 0; n2 < 4; n2++) {
            const int col = bn + wc * 32 + n2 * 8 + (lid & 3) * 2;
            const float b0 = __ldg(bias + col);
            const float b1 = __ldg(bias + col + 1);
            float v0 = acc[m2][n2][0] + b0;
            float v1 = acc[m2][n2][1] + b1;
            float v2 = acc[m2][n2][2] + b0;
            float v3 = acc[m2][n2][3] + b1;
            if (ACT == 1) {
                v0 = v0 > 0.f ? v0 + 1.f : expf(v0);
                v1 = v1 > 0.f ? v1 + 1.f : expf(v1);
                v2 = v2 > 0.f ? v2 + 1.f : expf(v2);
                v3 = v3 > 0.f ? v3 + 1.f : expf(v3);
            }
            float2 o0; o0.x = v0; o0.y = v1;
            float2 o1; o1.x = v2; o1.y = v3;
            *(float2*)(C + (size_t)row * EMB + col) = o0;
            *(float2*)(C + (size_t)(row + 8) * EMB + col) = o1;
        }
    }
}

// ---------------------------------------------------------------------------
// KtV + ksum, split 4-way over the attention axis
// ---------------------------------------------------------------------------
__global__ __launch_bounds__(256, 2)
void ktv_kernel(const float* __restrict__ Kp,
                const float* __restrict__ Vp,
                float* __restrict__ KtVp,
                float* __restrict__ ksump)
{
    const int g  = blockIdx.x;
    const int ch = blockIdx.y;
    const int bs = g >> 3;
    const int h  = g & 7;
    const size_t rowbase = (size_t)bs * ALEN;
    const int coff = h * HDIM;

    __shared__ float Ks[32][HDIM];
    __shared__ float Vs[32][HDIM];

    const int t  = threadIdx.x;
    const int tx = t & 15;
    const int ty = t >> 4;

    float acc[4][4];
    #pragma unroll
    for (int i = 0; i < 4; i++)
        #pragma unroll
        for (int j = 0; j < 4; j++)
            acc[i][j] = 0.f;
    float kcol = 0.f;

    for (int a0 = ch * ACH; a0 < (ch + 1) * ACH; a0 += 32) {
        #pragma unroll
        for (int i = 0; i < 2; i++) {
            const int idx = t * 2 + i;
            const int r   = idx >> 4;
            const int c4  = (idx & 15) * 4;
            const size_t goff = (rowbase + a0 + r) * EMB + coff + c4;
            *(float4*)&Ks[r][c4] = *(const float4*)(Kp + goff);
            *(float4*)&Vs[r][c4] = *(const float4*)(Vp + goff);
        }
        __syncthreads();

        #pragma unroll 8
        for (int r = 0; r < 32; r++) {
            float kf[4], vf[4];
            *(float4*)kf = *(const float4*)&Ks[r][ty * 4];
            *(float4*)vf = *(const float4*)&Vs[r][tx * 4];
            #pragma unroll
            for (int i = 0; i < 4; i++)
                #pragma unroll
                for (int j = 0; j < 4; j++)
                    acc[i][j] += kf[i] * vf[j];
        }
        if (t < HDIM) {
            #pragma unroll 8
            for (int r = 0; r < 32; r++) kcol += Ks[r][t];
        }
        __syncthreads();
    }

    float* out = KtVp + ((size_t)ch * NGROUP + g) * HDIM * HDIM;
    #pragma unroll
    for (int i = 0; i < 4; i++)
        #pragma unroll
        for (int j = 0; j < 4; j++)
            out[(ty * 4 + i) * HDIM + tx * 4 + j] = acc[i][j];
    if (t < HDIM) ksump[((size_t)ch * NGROUP + g) * HDIM + t] = kcol;
}

__global__ __launch_bounds__(256)
void ktv_reduce_kernel(const float* __restrict__ KtVp,
                       const float* __restrict__ ksump,
                       float* __restrict__ KtV,
                       float* __restrict__ ksum)
{
    const int g = blockIdx.x;
    const int t = threadIdx.x;
    #pragma unroll
    for (int i = t; i < HDIM * HDIM; i += 256) {
        float s = 0.f;
        #pragma unroll
        for (int p = 0; p < KSPLIT; p++)
            s += KtVp[((size_t)p * NGROUP + g) * HDIM * HDIM + i];
        KtV[(size_t)g * HDIM * HDIM + i] = s;
    }
    if (t < HDIM) {
        float s = 0.f;
        #pragma unroll
        for (int p = 0; p < KSPLIT; p++)
            s += ksump[((size_t)p * NGROUP + g) * HDIM + t];
        ksum[(size_t)g * HDIM + t] = s;
    }
}

// ===========================================================================
// Tensorized apply: per group g, per 128-token tile:
//   M = [KtV | ksum | 0-pad]  (64 x 72, col 64 = ksum)
//   C = Qtile(128x64) @ M ; z = 1/(C[:,64]+eps); AO = z * C[:,0:64]
// 256 threads = 8 warps, warp = 16 token rows; ntiles 9 (n=72), ks 8.
// ===========================================================================
#define AQ_S 68          // sQ row stride (words)
#define AM_S 72          // sM row stride (words)
#define APPLY_SMEM ((128 * AQ_S + 64 * AM_S) * 4)   // 53248 B

__global__ __launch_bounds__(256, 3)
void apply_mma_kernel(const float* __restrict__ Qp,
                      const float* __restrict__ KtV,
                      const float* __restrict__ ksum,
                      float* __restrict__ AO)
{
    extern __shared__ uint32_t sm[];
    uint32_t* sQ = sm;                 // [128][68]
    uint32_t* sM = sm + 128 * AQ_S;    // [64][72]

    const int g    = blockIdx.y;
    const int tile = blockIdx.x;
    const int bs   = g >> 3;
    const int h    = g & 7;
    const int t    = threadIdx.x;
    const int lid  = t & 31;
    const int wid  = t >> 5;           // 0..7

    // fill sM: KtV (tf32) + ksum column
    {
        const float* Ksrc = KtV + (size_t)g * HDIM * HDIM;
        #pragma unroll
        for (int i = t; i < 1024; i += 256) {
            const int d  = i >> 4;
            const int e0 = (i & 15) * 4;
            const float4 v = *(const float4*)(Ksrc + d * HDIM + e0);
            uint4 o;
            o.x = f2tf(v.x); o.y = f2tf(v.y); o.z = f2tf(v.z); o.w = f2tf(v.w);
            *(uint4*)&sM[d * AM_S + e0] = o;
        }
        if (t < HDIM)
            sM[t * AM_S + 64] = f2tf(ksum[(size_t)g * HDIM + t]);
    }
    // fill sQ: 128 token rows x 64 (tf32)
    {
        const int row = t >> 1;
        const int cb  = (t & 1) * 32;
        const float* qsrc = Qp + ((size_t)bs * ALEN + tile * 128 + row) * EMB + h * HDIM + cb;
        #pragma unroll
        for (int s = 0; s < 8; s++) {
            const float4 v = *(const float4*)(qsrc + s * 4);
            uint4 o;
            o.x = f2tf(v.x); o.y = f2tf(v.y); o.z = f2tf(v.z); o.w = f2tf(v.w);
            *(uint4*)&sQ[row * AQ_S + cb + s * 4] = o;
        }
    }
    __syncthreads();

    float acc[9][4];
    #pragma unroll
    for (int i = 0; i < 9; i++)
        #pragma unroll
        for (int j = 0; j < 4; j++)
            acc[i][j] = 0.f;

    #pragma unroll
    for (int ks = 0; ks < 8; ks++) {
        uint32_t aF[4];
        #pragma unroll
        for (int rg = 0; rg < 4; rg++) {
            const int row = wid * 16 + (lid >> 2) + 8 * (rg & 1);
            const int k   = ks * 8 + (lid & 3) + 4 * (rg >> 1);
            aF[rg] = sQ[row * AQ_S + k];
        }
        #pragma unroll
        for (int n2 = 0; n2 < 9; n2++) {
            uint32_t bF[2];
            const int n = n2 * 8 + (lid >> 2);
            bF[0] = sM[(ks * 8 + (lid & 3)) * AM_S + n];
            bF[1] = sM[(ks * 8 + 4 + (lid & 3)) * AM_S + n];
            mma8(acc[n2], aF, bF);
        }
    }

    // z from column 64 (ntile 8, lanes l&3==0 hold it in c0/c2)
    const float den0 = __shfl_sync(0xffffffffu, acc[8][0], lid & ~3);
    const float den1 = __shfl_sync(0xffffffffu, acc[8][2], lid & ~3);
    const float z0 = 1.f / (den0 + EPS_F);
    const float z1 = 1.f / (den1 + EPS_F);

    const int arow = tile * 128 + wid * 16 + (lid >> 2);
    const size_t base = ((size_t)bs * ALEN + arow) * EMB + h * HDIM;
    #pragma unroll
    for (int n2 = 0; n2 < 8; n2++) {
        const int col = n2 * 8 + (lid & 3) * 2;
        float2 o0; o0.x = z0 * acc[n2][0]; o0.y = z0 * acc[n2][1];
        float2 o1; o1.x = z1 * acc[n2][2]; o1.y = z1 * acc[n2][3];
        *(float2*)(AO + base + col) = o0;
        *(float2*)(AO + base + (size_t)8 * EMB + col) = o1;
    }
}

// ---------------------------------------------------------------------------
extern "C" void kernel_launch(void* const* d_in, const int* in_sizes, int n_in,
                              void* d_out, int out_size)
{
    const float* input_q  = (const float*)d_in[0];
    const float* input_kv = (const float*)d_in[1];
    const float* Wq = (const float*)d_in[2];
    const float* bq = (const float*)d_in[3];
    const float* Wk = (const float*)d_in[4];
    const float* bk = (const float*)d_in[5];
    const float* Wv = (const float*)d_in[6];
    const float* bv = (const float*)d_in[7];
    const float* Wo = (const float*)d_in[8];
    const float* bo = (const float*)d_in[9];
    float* out = (float*)d_out;

    void *pQ, *pK, *pV, *pAO, *pKtVp, *pksp, *pKtV, *pks, *pWf;
    cudaGetSymbolAddress(&pQ,    g_Q);
    cudaGetSymbolAddress(&pK,    g_K);
    cudaGetSymbolAddress(&pV,    g_V);
    cudaGetSymbolAddress(&pAO,   g_AO);
    cudaGetSymbolAddress(&pKtVp, g_KtVp);
    cudaGetSymbolAddress(&pksp,  g_ksump);
    cudaGetSymbolAddress(&pKtV,  g_KtV);
    cudaGetSymbolAddress(&pks,   g_ksum);
    cudaGetSymbolAddress(&pWf,   g_Wf);
    float*    Q    = (float*)pQ;
    float*    Kb   = (float*)pK;
    float*    Vb   = (float*)pV;
    float*    AO   = (float*)pAO;
    float*    KtVp = (float*)pKtVp;
    float*    ksp  = (float*)pksp;
    float*    KtV  = (float*)pKtV;
    float*    ks   = (float*)pks;
    uint32_t* Wf   = (uint32_t*)pWf;

    cudaFuncSetAttribute(gemm_mma2_kernel<0>,
                         cudaFuncAttributeMaxDynamicSharedMemorySize, GEMM_SMEM);
    cudaFuncSetAttribute(gemm_mma2_kernel<1>,
                         cudaFuncAttributeMaxDynamicSharedMemorySize, GEMM_SMEM);
    cudaFuncSetAttribute(apply_mma_kernel,
                         cudaFuncAttributeMaxDynamicSharedMemorySize, APPLY_SMEM);

    const size_t WSZ = (size_t)EMB * EMB;

    // Permute weights into fragment order (tf32)
    wprep_kernel<<<1024, 256>>>(Wq, Wf + 0 * WSZ);
    wprep_kernel<<<1024, 256>>>(Wk, Wf + 1 * WSZ);
    wprep_kernel<<<1024, 256>>>(Wv, Wf + 2 * WSZ);
    wprep_kernel<<<1024, 256>>>(Wo, Wf + 3 * WSZ);

    const dim3 ggrid(2, M_TOK / 64);   // (2, 2048)

    gemm_mma2_kernel<1><<<ggrid, 512, GEMM_SMEM>>>(input_q,  Wf + 0 * WSZ, bq, Q);
    gemm_mma2_kernel<1><<<ggrid, 512, GEMM_SMEM>>>(input_kv, Wf + 1 * WSZ, bk, Kb);
    gemm_mma2_kernel<0><<<ggrid, 512, GEMM_SMEM>>>(input_kv, Wf + 2 * WSZ, bv, Vb);

    ktv_kernel<<<dim3(NGROUP, KSPLIT), 256>>>(Kb, Vb, KtVp, ksp);
    ktv_reduce_kernel<<<NGROUP, 256>>>(KtVp, ksp, KtV, ks);
    apply_mma_kernel<<<dim3(ALEN / 128, NGROUP), 256, APPLY_SMEM>>>(Q, KtV, ks, AO);

    gemm_mma2_kernel<0><<<ggrid, 512, GEMM_SMEM>>>(AO, Wf + 3 * WSZ, bo, out);
}

// round 5
// speedup vs baseline: 2.8364x; 1.1335x over previous
#include <cuda_runtime.h>
#include <cuda_bf16.h>
#include <cstdint>

// Problem constants
#define M_TOK   131072      // b*s*a = 2*32*2048
#define EMB     512
#define NHEAD   8
#define HDIM    64
#define NGROUP  512         // b*s*h = 64*8
#define ALEN    2048
#define EPS_F   1e-6f
#define KSPLIT  8
#define ACH     (ALEN / KSPLIT)   // 256

// Scratch (device globals: allocation-free per harness rules)
__device__ float    g_Q [(size_t)M_TOK * EMB];
__device__ float    g_K [(size_t)M_TOK * EMB];
__device__ float    g_V [(size_t)M_TOK * EMB];
__device__ float    g_AO[(size_t)M_TOK * EMB];
__device__ float    g_KtVp [(size_t)KSPLIT * NGROUP * HDIM * HDIM];
__device__ float    g_ksump[(size_t)KSPLIT * NGROUP * HDIM];
__device__ float    g_KtV  [(size_t)NGROUP * HDIM * HDIM];
__device__ float    g_ksum [(size_t)NGROUP * HDIM];
__device__ uint32_t g_Wf [4 * (size_t)EMB * EMB];   // fragment-permuted tf32 weights

// ---------------------------------------------------------------------------
__device__ __forceinline__ uint32_t f2tf(float f) {
    uint32_t r;
    asm("cvt.rna.tf32.f32 %0, %1;" : "=r"(r) : "f"(f));
    return r;
}

__device__ __forceinline__ void mma8(float* d, const uint32_t* a, const uint32_t* b) {
    asm volatile(
        "mma.sync.aligned.m16n8k8.row.col.f32.tf32.tf32.f32 "
        "{%0,%1,%2,%3},{%4,%5,%6,%7},{%8,%9},{%0,%1,%2,%3};"
        : "+f"(d[0]), "+f"(d[1]), "+f"(d[2]), "+f"(d[3])
        : "r"(a[0]), "r"(a[1]), "r"(a[2]), "r"(a[3]),
          "r"(b[0]), "r"(b[1]));
}

__device__ __forceinline__ uint32_t smem_u32(const void* p) {
    uint32_t a;
    asm("{ .reg .u64 t; cvta.to.shared.u64 t, %1; cvt.u32.u64 %0, t; }"
        : "=r"(a) : "l"(p));
    return a;
}

__device__ __forceinline__ void cp16(uint32_t dst, const void* src) {
    asm volatile("cp.async.cg.shared.global [%0], [%1], 16;"
                 :: "r"(dst), "l"(src) : "memory");
}
#define CP_COMMIT() asm volatile("cp.async.commit_group;" ::: "memory")
#define CP_WAIT1()  asm volatile("cp.async.wait_group 1;" ::: "memory")
#define CP_WAIT0()  asm volatile("cp.async.wait_group 0;" ::: "memory")

// Validated fragment mapping (round-3/4 ground truth):
//   A (m16n8k8): lane l, reg rg holds A[(l>>2)+8*(rg&1)][(l&3)+4*(rg>>1)]
//   B:           lane l, reg rg holds B[k=(l&3)+4*rg][n=(l>>2)]
//   C:           lane l, reg c:  row=(l>>2)+8*(c>>1), col=(l&3)*2+(c&1)

// ===========================================================================
// Weight prep: permute W[512,512] ([K,N] row-major) into fragment order:
//   Wf[c(16)][ks(4)][ntg(64)][lane(32)][rg(2)] =
//     tf32(W[c*32+ks*8+(l&3)+4*rg][ntg*8+(l>>2)])
// ===========================================================================
__global__ __launch_bounds__(256)
void wprep_kernel(const float* __restrict__ W, uint32_t* __restrict__ Wf)
{
    const int o   = blockIdx.x * 256 + threadIdx.x;
    const int rg  = o & 1;
    const int l   = (o >> 1) & 31;
    const int ntg = (o >> 6) & 63;
    const int ks  = (o >> 12) & 3;
    const int c   = o >> 14;
    const int k   = c * 32 + ks * 8 + (l & 3) + 4 * rg;
    const int n   = ntg * 8 + (l >> 2);
    Wf[o] = f2tf(W[(size_t)k * EMB + n]);
}

// ===========================================================================
// tf32 mma GEMM, cp.async 3-stage pipeline.
// C[M,512] = act(A[M,512] @ W + bias), W pre-permuted (fragment order).
// BM=128, BN=128, BK=32. 256 threads = 8 warps (4 M x 2 N), warp tile 32x64.
// A smem: stride-44 rows (16B-aligned cp.async dst; fragment gather hits all
// 32 banks: (row*44+k)%32 = (row*12+k)%32 covers 0..31).
// B smem: flat copy of pre-permuted gmem slice; LDS.64 conflict-free.
// One __syncthreads per K-chunk.
// ===========================================================================
#define AS_W    44
#define A_STG   (128 * AS_W)          // 5632 words
#define B_STG   4096                  // words
#define STG_W   (A_STG + B_STG)       // 9728 words
#define GEMM_SMEM (3 * STG_W * 4)     // 116736 B

template<int ACT>
__global__ __launch_bounds__(256)
void gemm_mma3_kernel(const float* __restrict__ A,
                      const uint32_t* __restrict__ Wf,
                      const float* __restrict__ bias,
                      float* __restrict__ C)
{
    extern __shared__ uint32_t sm[];
    const uint32_t smb = smem_u32(sm);

    const int t   = threadIdx.x;
    const int lid = t & 31;
    const int wid = t >> 5;
    const int wr  = wid >> 1;          // 0..3 (M)
    const int wc  = wid & 1;           // 0..1 (N)
    const int bx  = blockIdx.x;        // 0..3 (N quarter)
    const int bm  = blockIdx.y * 128;

    const uint4* W4 = (const uint4*)Wf;

    // issue one K-chunk c into stage s
    auto issue = [&](int c, int s) {
        const uint32_t st = smb + (uint32_t)s * (STG_W * 4);
        // A: 128 rows x 32 floats = 1024 x 16B
        #pragma unroll
        for (int i = 0; i < 4; i++) {
            const int id  = t + i * 256;
            const int row = id >> 3;
            const int j   = id & 7;
            cp16(st + row * (AS_W * 4) + j * 16,
                 A + (size_t)(bm + row) * EMB + c * 32 + j * 4);
        }
        // B: 1024 x 16B, layout-preserving copy of this CTA's n-slice
        #pragma unroll
        for (int i = 0; i < 4; i++) {
            const int id   = t + i * 256;
            const int ks   = id >> 8;
            const int rest = id & 255;
            cp16(st + (A_STG + (ks * 256 + rest) * 4) * 4,
                 W4 + (size_t)((c * 4 + ks) * 64 + bx * 16) * 16 + rest);
        }
        CP_COMMIT();
    };

    float acc[2][8][4];
    #pragma unroll
    for (int i = 0; i < 2; i++)
        #pragma unroll
        for (int j = 0; j < 8; j++)
            #pragma unroll
            for (int k = 0; k < 4; k++)
                acc[i][j][k] = 0.f;

    issue(0, 0);
    issue(1, 1);

    for (int c = 0; c < 16; c++) {
        const int s = c % 3;
        if (c >= 14) { CP_WAIT0(); } else { CP_WAIT1(); }
        __syncthreads();
        if (c + 2 < 16) issue(c + 2, (c + 2) % 3);

        const uint32_t* Ab = sm + s * STG_W;
        const uint32_t* Bb = Ab + A_STG;

        #pragma unroll
        for (int ks = 0; ks < 4; ks++) {
            uint32_t aF[2][4];
            #pragma unroll
            for (int m2 = 0; m2 < 2; m2++)
                #pragma unroll
                for (int rg = 0; rg < 4; rg++) {
                    const int row = wr * 32 + m2 * 16 + (lid >> 2) + 8 * (rg & 1);
                    const int k   = ks * 8 + (lid & 3) + 4 * (rg >> 1);
                    aF[m2][rg] = Ab[row * AS_W + k];
                }
            uint32_t bF[8][2];
            #pragma unroll
            for (int n2 = 0; n2 < 8; n2++) {
                const uint2 v = *(const uint2*)
                    &Bb[((ks * 16 + wc * 8 + n2) * 32 + lid) * 2];
                bF[n2][0] = v.x; bF[n2][1] = v.y;
            }
            #pragma unroll
            for (int m2 = 0; m2 < 2; m2++)
                #pragma unroll
                for (int n2 = 0; n2 < 8; n2++)
                    mma8(acc[m2][n2], aF[m2], bF[n2]);
        }
    }

    // epilogue (validated C layout)
    const int bn = bx * 128;
    const int r0 = bm + wr * 32 + (lid >> 2);
    #pragma unroll
    for (int m2 = 0; m2 < 2; m2++) {
        const int row = r0 + m2 * 16;
        #pragma unroll
        for (int n2 = 0; n2 < 8; n2++) {
            const int col = bn + wc * 64 + n2 * 8 + (lid & 3) * 2;
            const float b0 = __ldg(bias + col);
            const float b1 = __ldg(bias + col + 1);
            float v0 = acc[m2][n2][0] + b0;
            float v1 = acc[m2][n2][1] + b1;
            float v2 = acc[m2][n2][2] + b0;
            float v3 = acc[m2][n2][3] + b1;
            if (ACT == 1) {
                v0 = v0 > 0.f ? v0 + 1.f : expf(v0);
                v1 = v1 > 0.f ? v1 + 1.f : expf(v1);
                v2 = v2 > 0.f ? v2 + 1.f : expf(v2);
                v3 = v3 > 0.f ? v3 + 1.f : expf(v3);
            }
            float2 o0; o0.x = v0; o0.y = v1;
            float2 o1; o1.x = v2; o1.y = v3;
            *(float2*)(C + (size_t)row * EMB + col) = o0;
            *(float2*)(C + (size_t)(row + 8) * EMB + col) = o1;
        }
    }
}

// ---------------------------------------------------------------------------
// KtV + ksum, split 8-way over the attention axis
// ---------------------------------------------------------------------------
__global__ __launch_bounds__(256, 2)
void ktv_kernel(const float* __restrict__ Kp,
                const float* __restrict__ Vp,
                float* __restrict__ KtVp,
                float* __restrict__ ksump)
{
    const int g  = blockIdx.x;
    const int ch = blockIdx.y;
    const int bs = g >> 3;
    const int h  = g & 7;
    const size_t rowbase = (size_t)bs * ALEN;
    const int coff = h * HDIM;

    __shared__ float Ks[32][HDIM];
    __shared__ float Vs[32][HDIM];

    const int t  = threadIdx.x;
    const int tx = t & 15;
    const int ty = t >> 4;

    float acc[4][4];
    #pragma unroll
    for (int i = 0; i < 4; i++)
        #pragma unroll
        for (int j = 0; j < 4; j++)
            acc[i][j] = 0.f;
    float kcol = 0.f;

    for (int a0 = ch * ACH; a0 < (ch + 1) * ACH; a0 += 32) {
        #pragma unroll
        for (int i = 0; i < 2; i++) {
            const int idx = t * 2 + i;
            const int r   = idx >> 4;
            const int c4  = (idx & 15) * 4;
            const size_t goff = (rowbase + a0 + r) * EMB + coff + c4;
            *(float4*)&Ks[r][c4] = *(const float4*)(Kp + goff);
            *(float4*)&Vs[r][c4] = *(const float4*)(Vp + goff);
        }
        __syncthreads();

        #pragma unroll 8
        for (int r = 0; r < 32; r++) {
            float kf[4], vf[4];
            *(float4*)kf = *(const float4*)&Ks[r][ty * 4];
            *(float4*)vf = *(const float4*)&Vs[r][tx * 4];
            #pragma unroll
            for (int i = 0; i < 4; i++)
                #pragma unroll
                for (int j = 0; j < 4; j++)
                    acc[i][j] += kf[i] * vf[j];
        }
        if (t < HDIM) {
            #pragma unroll 8
            for (int r = 0; r < 32; r++) kcol += Ks[r][t];
        }
        __syncthreads();
    }

    float* out = KtVp + ((size_t)ch * NGROUP + g) * HDIM * HDIM;
    #pragma unroll
    for (int i = 0; i < 4; i++)
        #pragma unroll
        for (int j = 0; j < 4; j++)
            out[(ty * 4 + i) * HDIM + tx * 4 + j] = acc[i][j];
    if (t < HDIM) ksump[((size_t)ch * NGROUP + g) * HDIM + t] = kcol;
}

__global__ __launch_bounds__(256)
void ktv_reduce_kernel(const float* __restrict__ KtVp,
                       const float* __restrict__ ksump,
                       float* __restrict__ KtV,
                       float* __restrict__ ksum)
{
    const int g = blockIdx.x;
    const int t = threadIdx.x;
    #pragma unroll
    for (int i = t; i < HDIM * HDIM; i += 256) {
        float s = 0.f;
        #pragma unroll
        for (int p = 0; p < KSPLIT; p++)
            s += KtVp[((size_t)p * NGROUP + g) * HDIM * HDIM + i];
        KtV[(size_t)g * HDIM * HDIM + i] = s;
    }
    if (t < HDIM) {
        float s = 0.f;
        #pragma unroll
        for (int p = 0; p < KSPLIT; p++)
            s += ksump[((size_t)p * NGROUP + g) * HDIM + t];
        ksum[(size_t)g * HDIM + t] = s;
    }
}

// ===========================================================================
// Tensorized apply (unchanged from R4, validated)
// ===========================================================================
#define AQ_S 68
#define AM_S 72
#define APPLY_SMEM ((128 * AQ_S + 64 * AM_S) * 4)

__global__ __launch_bounds__(256, 3)
void apply_mma_kernel(const float* __restrict__ Qp,
                      const float* __restrict__ KtV,
                      const float* __restrict__ ksum,
                      float* __restrict__ AO)
{
    extern __shared__ uint32_t sm[];
    uint32_t* sQ = sm;
    uint32_t* sM = sm + 128 * AQ_S;

    const int g    = blockIdx.y;
    const int tile = blockIdx.x;
    const int bs   = g >> 3;
    const int h    = g & 7;
    const int t    = threadIdx.x;
    const int lid  = t & 31;
    const int wid  = t >> 5;

    {
        const float* Ksrc = KtV + (size_t)g * HDIM * HDIM;
        #pragma unroll
        for (int i = t; i < 1024; i += 256) {
            const int d  = i >> 4;
            const int e0 = (i & 15) * 4;
            const float4 v = *(const float4*)(Ksrc + d * HDIM + e0);
            uint4 o;
            o.x = f2tf(v.x); o.y = f2tf(v.y); o.z = f2tf(v.z); o.w = f2tf(v.w);
            *(uint4*)&sM[d * AM_S + e0] = o;
        }
        if (t < HDIM)
            sM[t * AM_S + 64] = f2tf(ksum[(size_t)g * HDIM + t]);
    }
    {
        const int row = t >> 1;
        const int cb  = (t & 1) * 32;
        const float* qsrc = Qp + ((size_t)bs * ALEN + tile * 128 + row) * EMB + h * HDIM + cb;
        #pragma unroll
        for (int s = 0; s < 8; s++) {
            const float4 v = *(const float4*)(qsrc + s * 4);
            uint4 o;
            o.x = f2tf(v.x); o.y = f2tf(v.y); o.z = f2tf(v.z); o.w = f2tf(v.w);
            *(uint4*)&sQ[row * AQ_S + cb + s * 4] = o;
        }
    }
    __syncthreads();

    float acc[9][4];
    #pragma unroll
    for (int i = 0; i < 9; i++)
        #pragma unroll
        for (int j = 0; j < 4; j++)
            acc[i][j] = 0.f;

    #pragma unroll
    for (int ks = 0; ks < 8; ks++) {
        uint32_t aF[4];
        #pragma unroll
        for (int rg = 0; rg < 4; rg++) {
            const int row = wid * 16 + (lid >> 2) + 8 * (rg & 1);
            const int k   = ks * 8 + (lid & 3) + 4 * (rg >> 1);
            aF[rg] = sQ[row * AQ_S + k];
        }
        #pragma unroll
        for (int n2 = 0; n2 < 9; n2++) {
            uint32_t bF[2];
            const int n = n2 * 8 + (lid >> 2);
            bF[0] = sM[(ks * 8 + (lid & 3)) * AM_S + n];
            bF[1] = sM[(ks * 8 + 4 + (lid & 3)) * AM_S + n];
            mma8(acc[n2], aF, bF);
        }
    }

    const float den0 = __shfl_sync(0xffffffffu, acc[8][0], lid & ~3);
    const float den1 = __shfl_sync(0xffffffffu, acc[8][2], lid & ~3);
    const float z0 = 1.f / (den0 + EPS_F);
    const float z1 = 1.f / (den1 + EPS_F);

    const int arow = tile * 128 + wid * 16 + (lid >> 2);
    const size_t base = ((size_t)bs * ALEN + arow) * EMB + h * HDIM;
    #pragma unroll
    for (int n2 = 0; n2 < 8; n2++) {
        const int col = n2 * 8 + (lid & 3) * 2;
        float2 o0; o0.x = z0 * acc[n2][0]; o0.y = z0 * acc[n2][1];
        float2 o1; o1.x = z1 * acc[n2][2]; o1.y = z1 * acc[n2][3];
        *(float2*)(AO + base + col) = o0;
        *(float2*)(AO + base + (size_t)8 * EMB + col) = o1;
    }
}

// ---------------------------------------------------------------------------
extern "C" void kernel_launch(void* const* d_in, const int* in_sizes, int n_in,
                              void* d_out, int out_size)
{
    const float* input_q  = (const float*)d_in[0];
    const float* input_kv = (const float*)d_in[1];
    const float* Wq = (const float*)d_in[2];
    const float* bq = (const float*)d_in[3];
    const float* Wk = (const float*)d_in[4];
    const float* bk = (const float*)d_in[5];
    const float* Wv = (const float*)d_in[6];
    const float* bv = (const float*)d_in[7];
    const float* Wo = (const float*)d_in[8];
    const float* bo = (const float*)d_in[9];
    float* out = (float*)d_out;

    void *pQ, *pK, *pV, *pAO, *pKtVp, *pksp, *pKtV, *pks, *pWf;
    cudaGetSymbolAddress(&pQ,    g_Q);
    cudaGetSymbolAddress(&pK,    g_K);
    cudaGetSymbolAddress(&pV,    g_V);
    cudaGetSymbolAddress(&pAO,   g_AO);
    cudaGetSymbolAddress(&pKtVp, g_KtVp);
    cudaGetSymbolAddress(&pksp,  g_ksump);
    cudaGetSymbolAddress(&pKtV,  g_KtV);
    cudaGetSymbolAddress(&pks,   g_ksum);
    cudaGetSymbolAddress(&pWf,   g_Wf);
    float*    Q    = (float*)pQ;
    float*    Kb   = (float*)pK;
    float*    Vb   = (float*)pV;
    float*    AO   = (float*)pAO;
    float*    KtVp = (float*)pKtVp;
    float*    ksp  = (float*)pksp;
    float*    KtV  = (float*)pKtV;
    float*    ks   = (float*)pks;
    uint32_t* Wf   = (uint32_t*)pWf;

    cudaFuncSetAttribute(gemm_mma3_kernel<0>,
                         cudaFuncAttributeMaxDynamicSharedMemorySize, GEMM_SMEM);
    cudaFuncSetAttribute(gemm_mma3_kernel<1>,
                         cudaFuncAttributeMaxDynamicSharedMemorySize, GEMM_SMEM);
    cudaFuncSetAttribute(apply_mma_kernel,
                         cudaFuncAttributeMaxDynamicSharedMemorySize, APPLY_SMEM);

    const size_t WSZ = (size_t)EMB * EMB;

    wprep_kernel<<<1024, 256>>>(Wq, Wf + 0 * WSZ);
    wprep_kernel<<<1024, 256>>>(Wk, Wf + 1 * WSZ);
    wprep_kernel<<<1024, 256>>>(Wv, Wf + 2 * WSZ);
    wprep_kernel<<<1024, 256>>>(Wo, Wf + 3 * WSZ);

    const dim3 ggrid(4, M_TOK / 128);   // (4, 1024)

    gemm_mma3_kernel<1><<<ggrid, 256, GEMM_SMEM>>>(input_q,  Wf + 0 * WSZ, bq, Q);
    gemm_mma3_kernel<1><<<ggrid, 256, GEMM_SMEM>>>(input_kv, Wf + 1 * WSZ, bk, Kb);
    gemm_mma3_kernel<0><<<ggrid, 256, GEMM_SMEM>>>(input_kv, Wf + 2 * WSZ, bv, Vb);

    ktv_kernel<<<dim3(NGROUP, KSPLIT), 256>>>(Kb, Vb, KtVp, ksp);
    ktv_reduce_kernel<<<NGROUP, 256>>>(KtVp, ksp, KtV, ks);
    apply_mma_kernel<<<dim3(ALEN / 128, NGROUP), 256, APPLY_SMEM>>>(Q, KtV, ks, AO);

    gemm_mma3_kernel<0><<<ggrid, 256, GEMM_SMEM>>>(AO, Wf + 3 * WSZ, bo, out);
}

// round 6
// speedup vs baseline: 5.1419x; 1.8128x over previous
#include <cuda_runtime.h>
#include <cuda_fp16.h>
#include <cstdint>

// Problem constants
#define M_TOK   131072      // b*s*a = 2*32*2048
#define EMB     512
#define NHEAD   8
#define HDIM    64
#define NGROUP  512         // b*s*h = 64*8
#define ALEN    2048
#define EPS_F   1e-6f
#define KSPLIT  8
#define ACH     (ALEN / KSPLIT)   // 256

// Scratch (device globals: allocation-free per harness rules)
__device__ __half   g_iqh[(size_t)M_TOK * EMB];
__device__ __half   g_ikh[(size_t)M_TOK * EMB];
__device__ __half   g_Qh [(size_t)M_TOK * EMB];
__device__ __half   g_Kh [(size_t)M_TOK * EMB];
__device__ __half   g_Vh [(size_t)M_TOK * EMB];
__device__ __half   g_AOh[(size_t)M_TOK * EMB];
__device__ float    g_KtVp [(size_t)KSPLIT * NGROUP * HDIM * HDIM];
__device__ float    g_ksump[(size_t)KSPLIT * NGROUP * HDIM];
__device__ float    g_KtV  [(size_t)NGROUP * HDIM * HDIM];
__device__ float    g_ksum [(size_t)NGROUP * HDIM];
__device__ uint32_t g_Wf [4 * (size_t)131072];   // fragment-packed fp16 weights

// ---------------------------------------------------------------------------
__device__ __forceinline__ void mma16(float* d, const uint32_t* a, const uint32_t* b) {
    asm volatile(
        "mma.sync.aligned.m16n8k16.row.col.f32.f16.f16.f32 "
        "{%0,%1,%2,%3},{%4,%5,%6,%7},{%8,%9},{%0,%1,%2,%3};"
        : "+f"(d[0]), "+f"(d[1]), "+f"(d[2]), "+f"(d[3])
        : "r"(a[0]), "r"(a[1]), "r"(a[2]), "r"(a[3]),
          "r"(b[0]), "r"(b[1]));
}

__device__ __forceinline__ void ldmx4(uint32_t* r, uint32_t addr) {
    asm volatile("ldmatrix.sync.aligned.m8n8.x4.shared.b16 {%0,%1,%2,%3}, [%4];"
                 : "=r"(r[0]), "=r"(r[1]), "=r"(r[2]), "=r"(r[3]) : "r"(addr));
}

__device__ __forceinline__ uint32_t smem_u32(const void* p) {
    uint32_t a;
    asm("{ .reg .u64 t; cvta.to.shared.u64 t, %1; cvt.u32.u64 %0, t; }"
        : "=r"(a) : "l"(p));
    return a;
}

__device__ __forceinline__ void cp16(uint32_t dst, const void* src) {
    asm volatile("cp.async.cg.shared.global [%0], [%1], 16;"
                 :: "r"(dst), "l"(src) : "memory");
}
#define CP_COMMIT() asm volatile("cp.async.commit_group;" ::: "memory")
#define CP_WAIT1()  asm volatile("cp.async.wait_group 1;" ::: "memory")
#define CP_WAIT0()  asm volatile("cp.async.wait_group 0;" ::: "memory")

__device__ __forceinline__ uint32_t packh2(float a, float b) {
    __half2 h = __floats2half2_rn(a, b);
    return *(uint32_t*)&h;
}

// Fragment mapping (m16n8k16, validated family):
//   A: lane l, reg rg: pairs A[(l>>2)+8*(rg&1)][(l&3)*2 + 8*(rg>>1) + {0,1}]
//   B: lane l, reg rg: pairs B[k=(l&3)*2+8*rg+{0,1}][n=(l>>2)]
//   C: lane l, reg c:  row=(l>>2)+8*(c>>1), col=(l&3)*2+(c&1)

// ===========================================================================
// Prep: fp32 -> fp16 elementwise (8 per thread)
// ===========================================================================
__global__ __launch_bounds__(256)
void aprep_kernel(const float* __restrict__ src, __half* __restrict__ dst)
{
    const size_t i = ((size_t)blockIdx.x * 256 + threadIdx.x) * 8;
    const float4 a = *(const float4*)(src + i);
    const float4 b = *(const float4*)(src + i + 4);
    __half2 h[4];
    h[0] = __floats2half2_rn(a.x, a.y);
    h[1] = __floats2half2_rn(a.z, a.w);
    h[2] = __floats2half2_rn(b.x, b.y);
    h[3] = __floats2half2_rn(b.z, b.w);
    *(uint4*)(dst + i) = *(uint4*)h;
}

// ===========================================================================
// Weight prep: W[512,512] ([K,N] row-major) -> fp16 B-fragment order:
//   Wf[c(8)][ks(4)][ntg(64)][lane(32)][rg(2)] = pack(W[k0][n], W[k0+1][n])
//   k0 = c*64 + ks*16 + (l&3)*2 + 8*rg,  n = ntg*8 + (l>>2)
// ===========================================================================
__global__ __launch_bounds__(256)
void wprep_kernel(const float* __restrict__ W, uint32_t* __restrict__ Wf)
{
    const int o   = blockIdx.x * 256 + threadIdx.x;   // 0..131071
    const int rg  = o & 1;
    const int l   = (o >> 1) & 31;
    const int ntg = (o >> 6) & 63;
    const int ks  = (o >> 12) & 3;
    const int c   = o >> 14;
    const int k0  = c * 64 + ks * 16 + (l & 3) * 2 + 8 * rg;
    const int n   = ntg * 8 + (l >> 2);
    Wf[o] = packh2(W[(size_t)k0 * EMB + n], W[(size_t)(k0 + 1) * EMB + n]);
}

// ===========================================================================
// fp16 mma GEMM, cp.async 3-stage pipeline.
// C[M,512] = act(Ah[M,512] @ W + bias), W pre-packed fragment order.
// BM=128, BN=128, BK=64. 256 threads = 8 warps (4 M x 2 N), warp tile 32x64.
// A smem: rows of 64 fp16, stride 72 fp16 = 144B (ldmatrix conflict-free).
// B smem: flat copy of pre-packed gmem slice; LDS.64 conflict-free.
// ===========================================================================
#define AS_B    144                   // A row stride bytes
#define A_STG   (128 * 36)            // 4608 words
#define B_STG   4096                  // words
#define STG_W   (A_STG + B_STG)       // 8704 words
#define GEMM_SMEM (3 * STG_W * 4)     // 104448 B

template<int ACT, int OUTH>
__global__ __launch_bounds__(256)
void gemm_h_kernel(const __half* __restrict__ Ah,
                   const uint32_t* __restrict__ Wf,
                   const float* __restrict__ bias,
                   void* __restrict__ Cv)
{
    extern __shared__ uint32_t sm[];
    const uint32_t smb = smem_u32(sm);

    const int t   = threadIdx.x;
    const int lid = t & 31;
    const int wid = t >> 5;
    const int wr  = wid >> 1;          // 0..3 (M)
    const int wc  = wid & 1;           // 0..1 (N)
    const int bx  = blockIdx.x;        // 0..3 (N quarter)
    const int bm  = blockIdx.y * 128;

    const uint4* W4 = (const uint4*)Wf;

    auto issue = [&](int c, int s) {
        const uint32_t st = smb + (uint32_t)s * (STG_W * 4);
        // A: 128 rows x 64 fp16 = 1024 x 16B
        #pragma unroll
        for (int i = 0; i < 4; i++) {
            const int id  = t + i * 256;
            const int row = id >> 3;
            const int j   = id & 7;
            cp16(st + row * AS_B + j * 16,
                 Ah + (size_t)(bm + row) * EMB + c * 64 + j * 8);
        }
        // B: 1024 x 16B
        #pragma unroll
        for (int i = 0; i < 4; i++) {
            const int id   = t + i * 256;
            const int ks   = id >> 8;
            const int rest = id & 255;
            cp16(st + (A_STG + ks * 1024) * 4 + rest * 16,
                 W4 + (size_t)((c * 4 + ks) * 64 + bx * 16) * 16 + rest);
        }
        CP_COMMIT();
    };

    float acc[2][8][4];
    #pragma unroll
    for (int i = 0; i < 2; i++)
        #pragma unroll
        for (int j = 0; j < 8; j++)
            #pragma unroll
            for (int k = 0; k < 4; k++)
                acc[i][j][k] = 0.f;

    issue(0, 0);
    issue(1, 1);

    for (int c = 0; c < 8; c++) {
        const int s = c % 3;
        if (c >= 6) { CP_WAIT0(); } else { CP_WAIT1(); }
        __syncthreads();
        if (c + 2 < 8) issue(c + 2, (c + 2) % 3);

        const uint32_t stA = smb + (uint32_t)s * (STG_W * 4);
        const uint32_t* Bb = sm + s * STG_W + A_STG;

        #pragma unroll
        for (int ks = 0; ks < 4; ks++) {
            uint32_t aF[2][4];
            #pragma unroll
            for (int m2 = 0; m2 < 2; m2++)
                ldmx4(aF[m2], stA + (wr * 32 + m2 * 16 + (lid & 15)) * AS_B
                               + ks * 32 + (lid >> 4) * 16);
            uint32_t bF[8][2];
            #pragma unroll
            for (int n2 = 0; n2 < 8; n2++) {
                const uint2 v = *(const uint2*)
                    &Bb[ks * 1024 + (wc * 8 + n2) * 64 + lid * 2];
                bF[n2][0] = v.x; bF[n2][1] = v.y;
            }
            #pragma unroll
            for (int m2 = 0; m2 < 2; m2++)
                #pragma unroll
                for (int n2 = 0; n2 < 8; n2++)
                    mma16(acc[m2][n2], aF[m2], bF[n2]);
        }
    }

    // epilogue
    const int bn = bx * 128;
    const int r0 = bm + wr * 32 + (lid >> 2);
    #pragma unroll
    for (int m2 = 0; m2 < 2; m2++) {
        const int row = r0 + m2 * 16;
        #pragma unroll
        for (int n2 = 0; n2 < 8; n2++) {
            const int col = bn + wc * 64 + n2 * 8 + (lid & 3) * 2;
            const float b0 = __ldg(bias + col);
            const float b1 = __ldg(bias + col + 1);
            float v0 = acc[m2][n2][0] + b0;
            float v1 = acc[m2][n2][1] + b1;
            float v2 = acc[m2][n2][2] + b0;
            float v3 = acc[m2][n2][3] + b1;
            if (ACT == 1) {
                v0 = v0 > 0.f ? v0 + 1.f : expf(v0);
                v1 = v1 > 0.f ? v1 + 1.f : expf(v1);
                v2 = v2 > 0.f ? v2 + 1.f : expf(v2);
                v3 = v3 > 0.f ? v3 + 1.f : expf(v3);
            }
            if (OUTH) {
                __half* Ch = (__half*)Cv;
                *(uint32_t*)(Ch + (size_t)row * EMB + col)       = packh2(v0, v1);
                *(uint32_t*)(Ch + (size_t)(row + 8) * EMB + col) = packh2(v2, v3);
            } else {
                float* Cf = (float*)Cv;
                float2 o0; o0.x = v0; o0.y = v1;
                float2 o1; o1.x = v2; o1.y = v3;
                *(float2*)(Cf + (size_t)row * EMB + col) = o0;
                *(float2*)(Cf + (size_t)(row + 8) * EMB + col) = o1;
            }
        }
    }
}

// ---------------------------------------------------------------------------
// KtV + ksum, split 8-way, fp16 inputs (converted to fp32 in staging)
// ---------------------------------------------------------------------------
__global__ __launch_bounds__(256, 2)
void ktv_kernel(const __half* __restrict__ Kp,
                const __half* __restrict__ Vp,
                float* __restrict__ KtVp,
                float* __restrict__ ksump)
{
    const int g  = blockIdx.x;
    const int ch = blockIdx.y;
    const int bs = g >> 3;
    const int h  = g & 7;
    const size_t rowbase = (size_t)bs * ALEN;
    const int coff = h * HDIM;

    __shared__ float Ks[32][HDIM];
    __shared__ float Vs[32][HDIM];

    const int t  = threadIdx.x;
    const int tx = t & 15;
    const int ty = t >> 4;
    const int srow = t >> 3;     // 0..31
    const int sj   = t & 7;      // 0..7

    float acc[4][4];
    #pragma unroll
    for (int i = 0; i < 4; i++)
        #pragma unroll
        for (int j = 0; j < 4; j++)
            acc[i][j] = 0.f;
    float kcol = 0.f;

    for (int a0 = ch * ACH; a0 < (ch + 1) * ACH; a0 += 32) {
        const size_t goff = (rowbase + a0 + srow) * EMB + coff + sj * 8;
        {
            const uint4 kv = *(const uint4*)(Kp + goff);
            const __half2* hp = (const __half2*)&kv;
            #pragma unroll
            for (int e = 0; e < 4; e++) {
                const float2 f = __half22float2(hp[e]);
                Ks[srow][sj * 8 + e * 2]     = f.x;
                Ks[srow][sj * 8 + e * 2 + 1] = f.y;
            }
        }
        {
            const uint4 vv = *(const uint4*)(Vp + goff);
            const __half2* hp = (const __half2*)&vv;
            #pragma unroll
            for (int e = 0; e < 4; e++) {
                const float2 f = __half22float2(hp[e]);
                Vs[srow][sj * 8 + e * 2]     = f.x;
                Vs[srow][sj * 8 + e * 2 + 1] = f.y;
            }
        }
        __syncthreads();

        #pragma unroll 8
        for (int r = 0; r < 32; r++) {
            float kf[4], vf[4];
            *(float4*)kf = *(const float4*)&Ks[r][ty * 4];
            *(float4*)vf = *(const float4*)&Vs[r][tx * 4];
            #pragma unroll
            for (int i = 0; i < 4; i++)
                #pragma unroll
                for (int j = 0; j < 4; j++)
                    acc[i][j] += kf[i] * vf[j];
        }
        if (t < HDIM) {
            #pragma unroll 8
            for (int r = 0; r < 32; r++) kcol += Ks[r][t];
        }
        __syncthreads();
    }

    float* out = KtVp + ((size_t)ch * NGROUP + g) * HDIM * HDIM;
    #pragma unroll
    for (int i = 0; i < 4; i++)
        #pragma unroll
        for (int j = 0; j < 4; j++)
            out[(ty * 4 + i) * HDIM + tx * 4 + j] = acc[i][j];
    if (t < HDIM) ksump[((size_t)ch * NGROUP + g) * HDIM + t] = kcol;
}

__global__ __launch_bounds__(256)
void ktv_reduce_kernel(const float* __restrict__ KtVp,
                       const float* __restrict__ ksump,
                       float* __restrict__ KtV,
                       float* __restrict__ ksum)
{
    const int g = blockIdx.x;
    const int t = threadIdx.x;
    #pragma unroll
    for (int i = t; i < HDIM * HDIM; i += 256) {
        float s = 0.f;
        #pragma unroll
        for (int p = 0; p < KSPLIT; p++)
            s += KtVp[((size_t)p * NGROUP + g) * HDIM * HDIM + i];
        KtV[(size_t)g * HDIM * HDIM + i] = s;
    }
    if (t < HDIM) {
        float s = 0.f;
        #pragma unroll
        for (int p = 0; p < KSPLIT; p++)
            s += ksump[((size_t)p * NGROUP + g) * HDIM + t];
        ksum[(size_t)g * HDIM + t] = s;
    }
}

// ===========================================================================
// fp16 tensorized apply: C = Qtile(128x64) @ [KtV | ksum]; z=1/(C[:,64]+eps);
// AO = z * C[:,0:64], written fp16.
// sQ: [128 rows][72 fp16] (ldmatrix); sM: [32 packed-k rows][72 u32].
// ===========================================================================
#define AQ_B  144                           // sQ row stride bytes
#define SM_S  72                            // sM row stride words
#define APPLY_SMEM ((128 * 36 + 32 * SM_S) * 4)   // 27648 B

__global__ __launch_bounds__(256, 4)
void apply_h_kernel(const __half* __restrict__ Qp,
                    const float* __restrict__ KtV,
                    const float* __restrict__ ksum,
                    __half* __restrict__ AO)
{
    extern __shared__ uint32_t sm[];
    const uint32_t sQb = smem_u32(sm);
    uint32_t* sM = sm + 128 * 36;

    const int g    = blockIdx.y;
    const int tile = blockIdx.x;
    const int bs   = g >> 3;
    const int h    = g & 7;
    const int t    = threadIdx.x;
    const int lid  = t & 31;
    const int wid  = t >> 5;

    // sM: packed (d,d+1) fp16 pairs of KtV columns + ksum at col 64
    {
        const float* Ksrc = KtV + (size_t)g * HDIM * HDIM;
        #pragma unroll
        for (int i = t; i < 32 * 64; i += 256) {
            const int d2 = i >> 6;
            const int e  = i & 63;
            sM[d2 * SM_S + e] = packh2(Ksrc[(2 * d2) * HDIM + e],
                                       Ksrc[(2 * d2 + 1) * HDIM + e]);
        }
        if (t < 32)
            sM[t * SM_S + 64] = packh2(ksum[(size_t)g * HDIM + 2 * t],
                                       ksum[(size_t)g * HDIM + 2 * t + 1]);
        if (t < 224) {   // zero cols 65..71
            const int d2 = t / 7;
            const int e  = 65 + t % 7;
            sM[d2 * SM_S + e] = 0u;
        }
    }
    // sQ: direct fp16 copy, rows of 64 fp16 (stride 72)
    {
        #pragma unroll
        for (int i = 0; i < 4; i++) {
            const int id  = t + i * 256;
            const int row = id >> 3;
            const int j   = id & 7;
            const uint4 v = *(const uint4*)
                (Qp + ((size_t)bs * ALEN + tile * 128 + row) * EMB + h * HDIM + j * 8);
            *(uint4*)((char*)sm + row * AQ_B + j * 16) = v;
        }
    }
    __syncthreads();

    float acc[9][4];
    #pragma unroll
    for (int i = 0; i < 9; i++)
        #pragma unroll
        for (int j = 0; j < 4; j++)
            acc[i][j] = 0.f;

    #pragma unroll
    for (int ks = 0; ks < 4; ks++) {
        uint32_t aF[4];
        ldmx4(aF, sQb + (wid * 16 + (lid & 15)) * AQ_B + ks * 32 + (lid >> 4) * 16);
        #pragma unroll
        for (int n2 = 0; n2 < 9; n2++) {
            uint32_t bF[2];
            const int n = n2 * 8 + (lid >> 2);
            bF[0] = sM[(ks * 8 + (lid & 3)) * SM_S + n];
            bF[1] = sM[(ks * 8 + 4 + (lid & 3)) * SM_S + n];
            mma16(acc[n2], aF, bF);
        }
    }

    const float den0 = __shfl_sync(0xffffffffu, acc[8][0], lid & ~3);
    const float den1 = __shfl_sync(0xffffffffu, acc[8][2], lid & ~3);
    const float z0 = 1.f / (den0 + EPS_F);
    const float z1 = 1.f / (den1 + EPS_F);

    const int arow = tile * 128 + wid * 16 + (lid >> 2);
    const size_t base = ((size_t)bs * ALEN + arow) * EMB + h * HDIM;
    #pragma unroll
    for (int n2 = 0; n2 < 8; n2++) {
        const int col = n2 * 8 + (lid & 3) * 2;
        *(uint32_t*)(AO + base + col) = packh2(z0 * acc[n2][0], z0 * acc[n2][1]);
        *(uint32_t*)(AO + base + (size_t)8 * EMB + col) =
            packh2(z1 * acc[n2][2], z1 * acc[n2][3]);
    }
}

// ---------------------------------------------------------------------------
extern "C" void kernel_launch(void* const* d_in, const int* in_sizes, int n_in,
                              void* d_out, int out_size)
{
    const float* input_q  = (const float*)d_in[0];
    const float* input_kv = (const float*)d_in[1];
    const float* Wq = (const float*)d_in[2];
    const float* bq = (const float*)d_in[3];
    const float* Wk = (const float*)d_in[4];
    const float* bk = (const float*)d_in[5];
    const float* Wv = (const float*)d_in[6];
    const float* bv = (const float*)d_in[7];
    const float* Wo = (const float*)d_in[8];
    const float* bo = (const float*)d_in[9];
    float* out = (float*)d_out;

    void *p0, *p1, *p2, *p3, *p4, *p5, *p6, *p7, *p8, *p9, *p10;
    cudaGetSymbolAddress(&p0,  g_iqh);
    cudaGetSymbolAddress(&p1,  g_ikh);
    cudaGetSymbolAddress(&p2,  g_Qh);
    cudaGetSymbolAddress(&p3,  g_Kh);
    cudaGetSymbolAddress(&p4,  g_Vh);
    cudaGetSymbolAddress(&p5,  g_AOh);
    cudaGetSymbolAddress(&p6,  g_KtVp);
    cudaGetSymbolAddress(&p7,  g_ksump);
    cudaGetSymbolAddress(&p8,  g_KtV);
    cudaGetSymbolAddress(&p9,  g_ksum);
    cudaGetSymbolAddress(&p10, g_Wf);
    __half*   iqh  = (__half*)p0;
    __half*   ikh  = (__half*)p1;
    __half*   Qh   = (__half*)p2;
    __half*   Kh   = (__half*)p3;
    __half*   Vh   = (__half*)p4;
    __half*   AOh  = (__half*)p5;
    float*    KtVp = (float*)p6;
    float*    ksp  = (float*)p7;
    float*    KtV  = (float*)p8;
    float*    ks   = (float*)p9;
    uint32_t* Wf   = (uint32_t*)p10;

    cudaFuncSetAttribute((const void*)gemm_h_kernel<0, 0>,
                         cudaFuncAttributeMaxDynamicSharedMemorySize, GEMM_SMEM);
    cudaFuncSetAttribute((const void*)gemm_h_kernel<0, 1>,
                         cudaFuncAttributeMaxDynamicSharedMemorySize, GEMM_SMEM);
    cudaFuncSetAttribute((const void*)gemm_h_kernel<1, 1>,
                         cudaFuncAttributeMaxDynamicSharedMemorySize, GEMM_SMEM);
    cudaFuncSetAttribute((const void*)apply_h_kernel,
                         cudaFuncAttributeMaxDynamicSharedMemorySize, APPLY_SMEM);

    const size_t WSZ = 131072;

    // fp32 -> fp16 input conversion
    aprep_kernel<<<32768, 256>>>(input_q,  iqh);
    aprep_kernel<<<32768, 256>>>(input_kv, ikh);

    // weight packing (fp16 fragment order)
    wprep_kernel<<<512, 256>>>(Wq, Wf + 0 * WSZ);
    wprep_kernel<<<512, 256>>>(Wk, Wf + 1 * WSZ);
    wprep_kernel<<<512, 256>>>(Wv, Wf + 2 * WSZ);
    wprep_kernel<<<512, 256>>>(Wo, Wf + 3 * WSZ);

    const dim3 ggrid(4, M_TOK / 128);   // (4, 1024)

    gemm_h_kernel<1, 1><<<ggrid, 256, GEMM_SMEM>>>(iqh, Wf + 0 * WSZ, bq, Qh);
    gemm_h_kernel<1, 1><<<ggrid, 256, GEMM_SMEM>>>(ikh, Wf + 1 * WSZ, bk, Kh);
    gemm_h_kernel<0, 1><<<ggrid, 256, GEMM_SMEM>>>(ikh, Wf + 2 * WSZ, bv, Vh);

    ktv_kernel<<<dim3(NGROUP, KSPLIT), 256>>>(Kh, Vh, KtVp, ksp);
    ktv_reduce_kernel<<<NGROUP, 256>>>(KtVp, ksp, KtV, ks);
    apply_h_kernel<<<dim3(ALEN / 128, NGROUP), 256, APPLY_SMEM>>>(Qh, KtV, ks, AOh);

    gemm_h_kernel<0, 0><<<ggrid, 256, GEMM_SMEM>>>(AOh, Wf + 3 * WSZ, bo, out);
}

// round 7
// speedup vs baseline: 6.1179x; 1.1898x over previous
#include <cuda_runtime.h>
#include <cuda_fp16.h>
#include <cstdint>

// Problem constants
#define M_TOK   131072      // b*s*a = 2*32*2048
#define EMB     512
#define NHEAD   8
#define HDIM    64
#define NGROUP  512         // b*s*h = 64*8
#define ALEN    2048
#define EPS_F   1e-6f

// Scratch (device globals: allocation-free per harness rules)
__device__ __half   g_iqh[(size_t)M_TOK * EMB];
__device__ __half   g_ikh[(size_t)M_TOK * EMB];
__device__ __half   g_Qh [(size_t)M_TOK * EMB];
__device__ __half   g_Kh [(size_t)M_TOK * EMB];
__device__ __half   g_Vh [(size_t)M_TOK * EMB];
__device__ __half   g_AOh[(size_t)M_TOK * EMB];
__device__ float    g_KtV [(size_t)NGROUP * HDIM * HDIM];
__device__ float    g_ksum[(size_t)NGROUP * HDIM];
__device__ uint32_t g_Wf [4 * (size_t)131072];   // fragment-packed fp16 weights

// ---------------------------------------------------------------------------
__device__ __forceinline__ void mma16(float* d, const uint32_t* a, const uint32_t* b) {
    asm volatile(
        "mma.sync.aligned.m16n8k16.row.col.f32.f16.f16.f32 "
        "{%0,%1,%2,%3},{%4,%5,%6,%7},{%8,%9},{%0,%1,%2,%3};"
        : "+f"(d[0]), "+f"(d[1]), "+f"(d[2]), "+f"(d[3])
        : "r"(a[0]), "r"(a[1]), "r"(a[2]), "r"(a[3]),
          "r"(b[0]), "r"(b[1]));
}

__device__ __forceinline__ void ldmx4(uint32_t* r, uint32_t addr) {
    asm volatile("ldmatrix.sync.aligned.m8n8.x4.shared.b16 {%0,%1,%2,%3}, [%4];"
                 : "=r"(r[0]), "=r"(r[1]), "=r"(r[2]), "=r"(r[3]) : "r"(addr));
}
__device__ __forceinline__ void ldmx4t(uint32_t* r, uint32_t addr) {
    asm volatile("ldmatrix.sync.aligned.m8n8.x4.trans.shared.b16 {%0,%1,%2,%3}, [%4];"
                 : "=r"(r[0]), "=r"(r[1]), "=r"(r[2]), "=r"(r[3]) : "r"(addr));
}
__device__ __forceinline__ void ldmx2t(uint32_t* r, uint32_t addr) {
    asm volatile("ldmatrix.sync.aligned.m8n8.x2.trans.shared.b16 {%0,%1}, [%2];"
                 : "=r"(r[0]), "=r"(r[1]) : "r"(addr));
}

__device__ __forceinline__ uint32_t smem_u32(const void* p) {
    uint32_t a;
    asm("{ .reg .u64 t; cvta.to.shared.u64 t, %1; cvt.u32.u64 %0, t; }"
        : "=r"(a) : "l"(p));
    return a;
}

__device__ __forceinline__ void cp16(uint32_t dst, const void* src) {
    asm volatile("cp.async.cg.shared.global [%0], [%1], 16;"
                 :: "r"(dst), "l"(src) : "memory");
}
#define CP_COMMIT() asm volatile("cp.async.commit_group;" ::: "memory")
#define CP_WAIT1()  asm volatile("cp.async.wait_group 1;" ::: "memory")
#define CP_WAIT0()  asm volatile("cp.async.wait_group 0;" ::: "memory")

__device__ __forceinline__ uint32_t packh2(float a, float b) {
    __half2 h = __floats2half2_rn(a, b);
    return *(uint32_t*)&h;
}

// Fragment mapping (m16n8k16, validated):
//   A: lane l, reg rg: pairs A[(l>>2)+8*(rg&1)][(l&3)*2 + 8*(rg>>1) + {0,1}]
//   B: lane l, reg rg: pairs B[k=(l&3)*2+8*rg+{0,1}][n=(l>>2)]
//   C: lane l, reg c:  row=(l>>2)+8*(c>>1), col=(l&3)*2+(c&1)

// ===========================================================================
// Prep: fp32 -> fp16 for both inputs in ONE launch (keeps GEMM at launch #6
// so ncu -s 5 -c 1 profiles the Q projection).
// ===========================================================================
#define APREP_BLKS_PER 32768
__global__ __launch_bounds__(256)
void aprep2_kernel(const float* __restrict__ s0, __half* __restrict__ d0,
                   const float* __restrict__ s1, __half* __restrict__ d1)
{
    const int b = blockIdx.x;
    const float* src = (b < APREP_BLKS_PER) ? s0 : s1;
    __half*      dst = (b < APREP_BLKS_PER) ? d0 : d1;
    const size_t i = ((size_t)(b & (APREP_BLKS_PER - 1)) * 256 + threadIdx.x) * 8;
    const float4 a = *(const float4*)(src + i);
    const float4 c = *(const float4*)(src + i + 4);
    __half2 h[4];
    h[0] = __floats2half2_rn(a.x, a.y);
    h[1] = __floats2half2_rn(a.z, a.w);
    h[2] = __floats2half2_rn(c.x, c.y);
    h[3] = __floats2half2_rn(c.z, c.w);
    *(uint4*)(dst + i) = *(uint4*)h;
}

// ===========================================================================
// Weight prep (unchanged, validated)
// ===========================================================================
__global__ __launch_bounds__(256)
void wprep_kernel(const float* __restrict__ W, uint32_t* __restrict__ Wf)
{
    const int o   = blockIdx.x * 256 + threadIdx.x;
    const int rg  = o & 1;
    const int l   = (o >> 1) & 31;
    const int ntg = (o >> 6) & 63;
    const int ks  = (o >> 12) & 3;
    const int c   = o >> 14;
    const int k0  = c * 64 + ks * 16 + (l & 3) * 2 + 8 * rg;
    const int n   = ntg * 8 + (l >> 2);
    Wf[o] = packh2(W[(size_t)k0 * EMB + n], W[(size_t)(k0 + 1) * EMB + n]);
}

// ===========================================================================
// fp16 mma GEMM (unchanged from R6, validated)
// ===========================================================================
#define AS_B    144
#define A_STG   (128 * 36)
#define B_STG   4096
#define STG_W   (A_STG + B_STG)
#define GEMM_SMEM (3 * STG_W * 4)

template<int ACT, int OUTH>
__global__ __launch_bounds__(256)
void gemm_h_kernel(const __half* __restrict__ Ah,
                   const uint32_t* __restrict__ Wf,
                   const float* __restrict__ bias,
                   void* __restrict__ Cv)
{
    extern __shared__ uint32_t sm[];
    const uint32_t smb = smem_u32(sm);

    const int t   = threadIdx.x;
    const int lid = t & 31;
    const int wid = t >> 5;
    const int wr  = wid >> 1;
    const int wc  = wid & 1;
    const int bx  = blockIdx.x;
    const int bm  = blockIdx.y * 128;

    const uint4* W4 = (const uint4*)Wf;

    auto issue = [&](int c, int s) {
        const uint32_t st = smb + (uint32_t)s * (STG_W * 4);
        #pragma unroll
        for (int i = 0; i < 4; i++) {
            const int id  = t + i * 256;
            const int row = id >> 3;
            const int j   = id & 7;
            cp16(st + row * AS_B + j * 16,
                 Ah + (size_t)(bm + row) * EMB + c * 64 + j * 8);
        }
        #pragma unroll
        for (int i = 0; i < 4; i++) {
            const int id   = t + i * 256;
            const int ks   = id >> 8;
            const int rest = id & 255;
            cp16(st + (A_STG + ks * 1024) * 4 + rest * 16,
                 W4 + (size_t)((c * 4 + ks) * 64 + bx * 16) * 16 + rest);
        }
        CP_COMMIT();
    };

    float acc[2][8][4];
    #pragma unroll
    for (int i = 0; i < 2; i++)
        #pragma unroll
        for (int j = 0; j < 8; j++)
            #pragma unroll
            for (int k = 0; k < 4; k++)
                acc[i][j][k] = 0.f;

    issue(0, 0);
    issue(1, 1);

    for (int c = 0; c < 8; c++) {
        const int s = c % 3;
        if (c >= 6) { CP_WAIT0(); } else { CP_WAIT1(); }
        __syncthreads();
        if (c + 2 < 8) issue(c + 2, (c + 2) % 3);

        const uint32_t stA = smb + (uint32_t)s * (STG_W * 4);
        const uint32_t* Bb = sm + s * STG_W + A_STG;

        #pragma unroll
        for (int ks = 0; ks < 4; ks++) {
            uint32_t aF[2][4];
            #pragma unroll
            for (int m2 = 0; m2 < 2; m2++)
                ldmx4(aF[m2], stA + (wr * 32 + m2 * 16 + (lid & 15)) * AS_B
                               + ks * 32 + (lid >> 4) * 16);
            uint32_t bF[8][2];
            #pragma unroll
            for (int n2 = 0; n2 < 8; n2++) {
                const uint2 v = *(const uint2*)
                    &Bb[ks * 1024 + (wc * 8 + n2) * 64 + lid * 2];
                bF[n2][0] = v.x; bF[n2][1] = v.y;
            }
            #pragma unroll
            for (int m2 = 0; m2 < 2; m2++)
                #pragma unroll
                for (int n2 = 0; n2 < 8; n2++)
                    mma16(acc[m2][n2], aF[m2], bF[n2]);
        }
    }

    const int bn = bx * 128;
    const int r0 = bm + wr * 32 + (lid >> 2);
    #pragma unroll
    for (int m2 = 0; m2 < 2; m2++) {
        const int row = r0 + m2 * 16;
        #pragma unroll
        for (int n2 = 0; n2 < 8; n2++) {
            const int col = bn + wc * 64 + n2 * 8 + (lid & 3) * 2;
            const float b0 = __ldg(bias + col);
            const float b1 = __ldg(bias + col + 1);
            float v0 = acc[m2][n2][0] + b0;
            float v1 = acc[m2][n2][1] + b1;
            float v2 = acc[m2][n2][2] + b0;
            float v3 = acc[m2][n2][3] + b1;
            if (ACT == 1) {
                v0 = v0 > 0.f ? v0 + 1.f : expf(v0);
                v1 = v1 > 0.f ? v1 + 1.f : expf(v1);
                v2 = v2 > 0.f ? v2 + 1.f : expf(v2);
                v3 = v3 > 0.f ? v3 + 1.f : expf(v3);
            }
            if (OUTH) {
                __half* Ch = (__half*)Cv;
                *(uint32_t*)(Ch + (size_t)row * EMB + col)       = packh2(v0, v1);
                *(uint32_t*)(Ch + (size_t)(row + 8) * EMB + col) = packh2(v2, v3);
            } else {
                float* Cf = (float*)Cv;
                float2 o0; o0.x = v0; o0.y = v1;
                float2 o1; o1.x = v2; o1.y = v3;
                *(float2*)(Cf + (size_t)row * EMB + col) = o0;
                *(float2*)(Cf + (size_t)(row + 8) * EMB + col) = o1;
            }
        }
    }
}

// ===========================================================================
// Tensorized KtV + ksum: per group g (512 CTAs):
//   A = K^T (64 x 2048, via ldmatrix.trans of row-major K tiles)
//   B = [V | ones | pad]  (2048 x 72+, .col via ldmatrix.trans)
//   C[d][0:64] = KtV, C[d][64] = ksum.
// 8 warps: mt = wid>>1 (16 d-rows each), nh = wid&1 (nh0: n0-39, nh1: n40-71).
// 3-stage cp.async, 64-token chunks. K smem stride 144B, V stride 176B
// (both provably conflict-free for ldmatrix.trans).
// ===========================================================================
#define KTV_KST   9216                 // 64*144
#define KTV_VST   11264                // 64*176
#define KTV_STG   (KTV_KST + KTV_VST)  // 20480
#define KTV_SMEM  (3 * KTV_STG)        // 61440

__global__ __launch_bounds__(256)
void ktv_mma_kernel(const __half* __restrict__ Kp,
                    const __half* __restrict__ Vp,
                    float* __restrict__ KtV,
                    float* __restrict__ ksum)
{
    extern __shared__ uint32_t sm[];
    const uint32_t smb = smem_u32(sm);

    const int g  = blockIdx.x;
    const int bs = g >> 3;
    const int h  = g & 7;
    const size_t rowbase = (size_t)bs * ALEN;
    const int coff = h * HDIM;

    const int t   = threadIdx.x;
    const int lid = t & 31;
    const int wid = t >> 5;
    const int mt  = wid >> 1;          // 0..3 (d tile)
    const int nh  = wid & 1;           // 0..1
    const int ntc = 5 - nh;            // ntiles this warp (5 or 4)
    const int n0  = nh * 40;

    // ones column (col 64 of V region) for all 3 stages; pad cols untouched
    // (garbage there only pollutes unused output columns).
    if (t < 64) {
        #pragma unroll
        for (int s = 0; s < 3; s++) {
            __half* vb = (__half*)((char*)sm + s * KTV_STG + KTV_KST);
            vb[t * 88 + 64] = __float2half(1.0f);
        }
    }

    auto issue = [&](int c, int s) {
        const uint32_t stK = smb + (uint32_t)s * KTV_STG;
        const uint32_t stV = stK + KTV_KST;
        const int a0 = c * 64;
        #pragma unroll
        for (int i = 0; i < 2; i++) {
            const int id  = t + i * 256;
            const int row = id >> 3;
            const int j   = id & 7;
            const size_t goff = (rowbase + a0 + row) * EMB + coff + j * 8;
            cp16(stK + row * 144 + j * 16, Kp + goff);
            cp16(stV + row * 176 + j * 16, Vp + goff);
        }
        CP_COMMIT();
    };

    float acc[5][4];
    #pragma unroll
    for (int i = 0; i < 5; i++)
        #pragma unroll
        for (int j = 0; j < 4; j++)
            acc[i][j] = 0.f;

    // lane address components for ldmatrix.trans
    const int g2 = lid >> 3;           // matrix index 0..3
    const int l8 = lid & 7;
    // A (K^T): m0:a0-7/d0, m1:a0-7/d8, m2:a8-15/d0, m3:a8-15/d8
    const int a_rowA = (g2 >> 1) * 8 + l8;
    const int a_colA = mt * 16 + (g2 & 1) * 8;
    // B (V): m0:a0-7/n0, m1:a8-15/n0, m2:a0-7/n8, m3:a8-15/n8
    const int a_rowB = (g2 & 1) * 8 + l8;
    const int a_colB = (g2 >> 1) * 8;
    // x2 (lanes 0-15 meaningful): m0:a0-7, m1:a8-15
    const int a_rowB2 = ((lid >> 3) & 1) * 8 + l8;

    issue(0, 0);
    issue(1, 1);

    for (int c = 0; c < 32; c++) {
        const int s = c % 3;
        if (c >= 30) { CP_WAIT0(); } else { CP_WAIT1(); }
        __syncthreads();
        if (c + 2 < 32) issue(c + 2, (c + 2) % 3);

        const uint32_t stK = smb + (uint32_t)s * KTV_STG;
        const uint32_t stV = stK + KTV_KST;

        #pragma unroll
        for (int ks = 0; ks < 4; ks++) {
            uint32_t aF[4];
            ldmx4t(aF, stK + (ks * 16 + a_rowA) * 144 + a_colA * 2);

            uint32_t bF[5][2];
            {
                uint32_t r4[4];
                ldmx4t(r4, stV + (ks * 16 + a_rowB) * 176 + (n0 + a_colB) * 2);
                bF[0][0] = r4[0]; bF[0][1] = r4[1];
                bF[1][0] = r4[2]; bF[1][1] = r4[3];
                ldmx4t(r4, stV + (ks * 16 + a_rowB) * 176 + (n0 + 16 + a_colB) * 2);
                bF[2][0] = r4[0]; bF[2][1] = r4[1];
                bF[3][0] = r4[2]; bF[3][1] = r4[3];
            }
            if (nh == 0) {
                uint32_t r2[2];
                ldmx2t(r2, stV + (ks * 16 + a_rowB2) * 176 + (n0 + 32) * 2);
                bF[4][0] = r2[0]; bF[4][1] = r2[1];
            }

            #pragma unroll
            for (int nt = 0; nt < 4; nt++)
                mma16(acc[nt], aF, bF[nt]);
            if (nh == 0)
                mma16(acc[4], aF, bF[4]);
        }
    }

    // epilogue: C[d][n], d-row = mt*16 + (l>>2) + 8*(c>>1)
    const int d0 = mt * 16 + (lid >> 2);
    float* Kout = KtV + (size_t)g * HDIM * HDIM;
    #pragma unroll
    for (int nt = 0; nt < 5; nt++) {
        if (nt >= ntc) break;
        const int n = n0 + nt * 8;
        if (n < 64) {
            const int col = n + (lid & 3) * 2;
            float2 o0; o0.x = acc[nt][0]; o0.y = acc[nt][1];
            float2 o1; o1.x = acc[nt][2]; o1.y = acc[nt][3];
            *(float2*)(Kout + d0 * HDIM + col) = o0;
            *(float2*)(Kout + (d0 + 8) * HDIM + col) = o1;
        } else {
            // n == 64: ksum column (col 64 -> lanes with (lid&3)==0, c0/c2)
            if ((lid & 3) == 0) {
                ksum[(size_t)g * HDIM + d0]     = acc[nt][0];
                ksum[(size_t)g * HDIM + d0 + 8] = acc[nt][2];
            }
        }
    }
}

// ===========================================================================
// fp16 tensorized apply (unchanged from R6, validated)
// ===========================================================================
#define AQ_B  144
#define SM_S  72
#define APPLY_SMEM ((128 * 36 + 32 * SM_S) * 4)

__global__ __launch_bounds__(256, 4)
void apply_h_kernel(const __half* __restrict__ Qp,
                    const float* __restrict__ KtV,
                    const float* __restrict__ ksum,
                    __half* __restrict__ AO)
{
    extern __shared__ uint32_t sm[];
    const uint32_t sQb = smem_u32(sm);
    uint32_t* sM = sm + 128 * 36;

    const int g    = blockIdx.y;
    const int tile = blockIdx.x;
    const int bs   = g >> 3;
    const int h    = g & 7;
    const int t    = threadIdx.x;
    const int lid  = t & 31;
    const int wid  = t >> 5;

    {
        const float* Ksrc = KtV + (size_t)g * HDIM * HDIM;
        #pragma unroll
        for (int i = t; i < 32 * 64; i += 256) {
            const int d2 = i >> 6;
            const int e  = i & 63;
            sM[d2 * SM_S + e] = packh2(Ksrc[(2 * d2) * HDIM + e],
                                       Ksrc[(2 * d2 + 1) * HDIM + e]);
        }
        if (t < 32)
            sM[t * SM_S + 64] = packh2(ksum[(size_t)g * HDIM + 2 * t],
                                       ksum[(size_t)g * HDIM + 2 * t + 1]);
        if (t < 224) {
            const int d2 = t / 7;
            const int e  = 65 + t % 7;
            sM[d2 * SM_S + e] = 0u;
        }
    }
    {
        #pragma unroll
        for (int i = 0; i < 4; i++) {
            const int id  = t + i * 256;
            const int row = id >> 3;
            const int j   = id & 7;
            const uint4 v = *(const uint4*)
                (Qp + ((size_t)bs * ALEN + tile * 128 + row) * EMB + h * HDIM + j * 8);
            *(uint4*)((char*)sm + row * AQ_B + j * 16) = v;
        }
    }
    __syncthreads();

    float acc[9][4];
    #pragma unroll
    for (int i = 0; i < 9; i++)
        #pragma unroll
        for (int j = 0; j < 4; j++)
            acc[i][j] = 0.f;

    #pragma unroll
    for (int ks = 0; ks < 4; ks++) {
        uint32_t aF[4];
        ldmx4(aF, sQb + (wid * 16 + (lid & 15)) * AQ_B + ks * 32 + (lid >> 4) * 16);
        #pragma unroll
        for (int n2 = 0; n2 < 9; n2++) {
            uint32_t bF[2];
            const int n = n2 * 8 + (lid >> 2);
            bF[0] = sM[(ks * 8 + (lid & 3)) * SM_S + n];
            bF[1] = sM[(ks * 8 + 4 + (lid & 3)) * SM_S + n];
            mma16(acc[n2], aF, bF);
        }
    }

    const float den0 = __shfl_sync(0xffffffffu, acc[8][0], lid & ~3);
    const float den1 = __shfl_sync(0xffffffffu, acc[8][2], lid & ~3);
    const float z0 = 1.f / (den0 + EPS_F);
    const float z1 = 1.f / (den1 + EPS_F);

    const int arow = tile * 128 + wid * 16 + (lid >> 2);
    const size_t base = ((size_t)bs * ALEN + arow) * EMB + h * HDIM;
    #pragma unroll
    for (int n2 = 0; n2 < 8; n2++) {
        const int col = n2 * 8 + (lid & 3) * 2;
        *(uint32_t*)(AO + base + col) = packh2(z0 * acc[n2][0], z0 * acc[n2][1]);
        *(uint32_t*)(AO + base + (size_t)8 * EMB + col) =
            packh2(z1 * acc[n2][2], z1 * acc[n2][3]);
    }
}

// ---------------------------------------------------------------------------
extern "C" void kernel_launch(void* const* d_in, const int* in_sizes, int n_in,
                              void* d_out, int out_size)
{
    const float* input_q  = (const float*)d_in[0];
    const float* input_kv = (const float*)d_in[1];
    const float* Wq = (const float*)d_in[2];
    const float* bq = (const float*)d_in[3];
    const float* Wk = (const float*)d_in[4];
    const float* bk = (const float*)d_in[5];
    const float* Wv = (const float*)d_in[6];
    const float* bv = (const float*)d_in[7];
    const float* Wo = (const float*)d_in[8];
    const float* bo = (const float*)d_in[9];
    float* out = (float*)d_out;

    void *p0, *p1, *p2, *p3, *p4, *p5, *p8, *p9, *p10;
    cudaGetSymbolAddress(&p0,  g_iqh);
    cudaGetSymbolAddress(&p1,  g_ikh);
    cudaGetSymbolAddress(&p2,  g_Qh);
    cudaGetSymbolAddress(&p3,  g_Kh);
    cudaGetSymbolAddress(&p4,  g_Vh);
    cudaGetSymbolAddress(&p5,  g_AOh);
    cudaGetSymbolAddress(&p8,  g_KtV);
    cudaGetSymbolAddress(&p9,  g_ksum);
    cudaGetSymbolAddress(&p10, g_Wf);
    __half*   iqh  = (__half*)p0;
    __half*   ikh  = (__half*)p1;
    __half*   Qh   = (__half*)p2;
    __half*   Kh   = (__half*)p3;
    __half*   Vh   = (__half*)p4;
    __half*   AOh  = (__half*)p5;
    float*    KtV  = (float*)p8;
    float*    ks   = (float*)p9;
    uint32_t* Wf   = (uint32_t*)p10;

    cudaFuncSetAttribute((const void*)gemm_h_kernel<0, 0>,
                         cudaFuncAttributeMaxDynamicSharedMemorySize, GEMM_SMEM);
    cudaFuncSetAttribute((const void*)gemm_h_kernel<0, 1>,
                         cudaFuncAttributeMaxDynamicSharedMemorySize, GEMM_SMEM);
    cudaFuncSetAttribute((const void*)gemm_h_kernel<1, 1>,
                         cudaFuncAttributeMaxDynamicSharedMemorySize, GEMM_SMEM);
    cudaFuncSetAttribute((const void*)ktv_mma_kernel,
                         cudaFuncAttributeMaxDynamicSharedMemorySize, KTV_SMEM);
    cudaFuncSetAttribute((const void*)apply_h_kernel,
                         cudaFuncAttributeMaxDynamicSharedMemorySize, APPLY_SMEM);

    const size_t WSZ = 131072;

    // 5 prep launches, then the Q GEMM is launch #6 (ncu -s 5 profiles it)
    wprep_kernel<<<512, 256>>>(Wq, Wf + 0 * WSZ);
    wprep_kernel<<<512, 256>>>(Wk, Wf + 1 * WSZ);
    wprep_kernel<<<512, 256>>>(Wv, Wf + 2 * WSZ);
    wprep_kernel<<<512, 256>>>(Wo, Wf + 3 * WSZ);
    aprep2_kernel<<<2 * APREP_BLKS_PER, 256>>>(input_q, iqh, input_kv, ikh);

    const dim3 ggrid(4, M_TOK / 128);   // (4, 1024)

    gemm_h_kernel<1, 1><<<ggrid, 256, GEMM_SMEM>>>(iqh, Wf + 0 * WSZ, bq, Qh);
    gemm_h_kernel<1, 1><<<ggrid, 256, GEMM_SMEM>>>(ikh, Wf + 1 * WSZ, bk, Kh);
    gemm_h_kernel<0, 1><<<ggrid, 256, GEMM_SMEM>>>(ikh, Wf + 2 * WSZ, bv, Vh);

    ktv_mma_kernel<<<NGROUP, 256, KTV_SMEM>>>(Kh, Vh, KtV, ks);
    apply_h_kernel<<<dim3(ALEN / 128, NGROUP), 256, APPLY_SMEM>>>(Qh, KtV, ks, AOh);

    gemm_h_kernel<0, 0><<<ggrid, 256, GEMM_SMEM>>>(AOh, Wf + 3 * WSZ, bo, out);
}